// round 2
// baseline (speedup 1.0000x reference)
#include <cuda_runtime.h>

#define BB 256
#define TT 127
#define TFULL 128
#define SS 256
#define DD 512
#define VV 50
#define HH 4
#define HDD 128
#define G3 1536

// -------------------- device scratch (no allocations allowed) --------------------
__device__ __align__(128) float g_K[(size_t)BB * HH * SS * HDD];   // [b][h][s][hd]
__device__ __align__(128) float g_V[(size_t)BB * HH * SS * HDD];   // [b][h][s][hd]
__device__ __align__(128) float g_h[BB * DD];
__device__ __align__(128) float g_q[BB * DD];        // pre-scaled q
__device__ __align__(128) float g_hg[BB * G3];       // h @ W_hh^T + b_hh
__device__ __align__(128) float g_ctx[BB * DD];
__device__ __align__(128) float g_xg[BB * G3];       // ctx@Wcombo^T + tproj[act] + bcombo
__device__ __align__(128) float g_Hseq[(size_t)TT * BB * DD];
__device__ __align__(128) float g_tproj[VV * G3];    // emb_table @ W_e^T + b_ih
__device__ __align__(128) float g_Wcombo[(size_t)G3 * DD]; // W_c @ Wo
__device__ __align__(128) float g_bcombo[G3];        // W_c @ bo

// -------------------- small helpers --------------------
__global__ void copy_h_kernel(const float* __restrict__ src) {
    int i = blockIdx.x * blockDim.x + threadIdx.x;
    g_h[i] = src[i];
}

__global__ void bcombo_kernel(const float* __restrict__ wih, const float* __restrict__ bo) {
    int n = blockIdx.x * 4 + (threadIdx.x >> 5);
    int lane = threadIdx.x & 31;
    const float* r = wih + (size_t)n * 1024 + 512;   // W_c row n
    float p = 0.f;
    for (int k = lane; k < DD; k += 32) p += r[k] * bo[k];
#pragma unroll
    for (int o = 16; o > 0; o >>= 1) p += __shfl_xor_sync(0xffffffffu, p, o);
    if (lane == 0) g_bcombo[n] = p;
}

// -------------------- generic TN GEMM, K=512 fixed --------------------
// C[m][n] = sum_k A[m][k] * Wrow(n)[k]  with per-EPI source/sink selection.
// EPI 0: tproj   (A=emb_table, W=gru_w_ih ld 1024, +b_ih  -> g_tproj)
// EPI 1: KV      (A=enc_seq,   W=in_proj_w+512*512, +b    -> scatter g_K/g_V)
// EPI 2: QH      (A=g_h, W=Wq / W2=gru_w_hh split at 512  -> g_q (scaled) / g_hg)
// EPI 3: XG      (A=g_ctx, W=g_Wcombo, + bcombo + tproj[act] -> g_xg)
template <int EPI>
__launch_bounds__(256)
__global__ void gemm_tn(const float* __restrict__ A, int lda,
                        const float* __restrict__ W, int ldw,
                        const float* __restrict__ W2, int ldw2, int nsplit,
                        const float* __restrict__ bias, const float* __restrict__ bias2,
                        int M, int N,
                        const int* __restrict__ act, int t) {
    __shared__ float As[16][68];
    __shared__ float Ws[16][68];
    const int bm = blockIdx.y * 64, bn = blockIdx.x * 64;
    const int tid = threadIdx.x;
    const int tx = tid & 15, ty = tid >> 4;
    const int lr = tid >> 2;            // 0..63
    const int lk = (tid & 3) << 2;      // 0,4,8,12

    const float* Abase = A;
    if (EPI == 2) Abase = g_h;
    if (EPI == 3) Abase = g_ctx;
    const float* Wbase = W;
    if (EPI == 3) Wbase = g_Wcombo;

    float acc[4][4];
#pragma unroll
    for (int i = 0; i < 4; i++)
#pragma unroll
        for (int j = 0; j < 4; j++) acc[i][j] = 0.f;

    const int gm_l = bm + lr;
    const int gn_l = bn + lr;
    const float* Arow = (gm_l < M) ? (Abase + (size_t)gm_l * lda) : nullptr;
    const float* Wrow;
    if (gn_l < nsplit) Wrow = Wbase + (size_t)gn_l * ldw;
    else Wrow = W2 + (size_t)(gn_l - nsplit) * ldw2;
    const bool wok = (gn_l < N);

    for (int k0 = 0; k0 < 512; k0 += 16) {
        float4 av = make_float4(0.f, 0.f, 0.f, 0.f);
        if (Arow) av = *(const float4*)(Arow + k0 + lk);
        float4 wv = make_float4(0.f, 0.f, 0.f, 0.f);
        if (wok) wv = *(const float4*)(Wrow + k0 + lk);
        As[lk + 0][lr] = av.x; As[lk + 1][lr] = av.y;
        As[lk + 2][lr] = av.z; As[lk + 3][lr] = av.w;
        Ws[lk + 0][lr] = wv.x; Ws[lk + 1][lr] = wv.y;
        Ws[lk + 2][lr] = wv.z; Ws[lk + 3][lr] = wv.w;
        __syncthreads();
#pragma unroll
        for (int kk = 0; kk < 16; kk++) {
            float4 a4 = *(const float4*)&As[kk][ty * 4];
            float4 w4 = *(const float4*)&Ws[kk][tx * 4];
            acc[0][0] += a4.x * w4.x; acc[0][1] += a4.x * w4.y;
            acc[0][2] += a4.x * w4.z; acc[0][3] += a4.x * w4.w;
            acc[1][0] += a4.y * w4.x; acc[1][1] += a4.y * w4.y;
            acc[1][2] += a4.y * w4.z; acc[1][3] += a4.y * w4.w;
            acc[2][0] += a4.z * w4.x; acc[2][1] += a4.z * w4.y;
            acc[2][2] += a4.z * w4.z; acc[2][3] += a4.z * w4.w;
            acc[3][0] += a4.w * w4.x; acc[3][1] += a4.w * w4.y;
            acc[3][2] += a4.w * w4.z; acc[3][3] += a4.w * w4.w;
        }
        __syncthreads();
    }

#pragma unroll
    for (int i = 0; i < 4; i++) {
        const int gm = bm + ty * 4 + i;
        if (gm >= M) continue;
#pragma unroll
        for (int j = 0; j < 4; j++) {
            const int gn = bn + tx * 4 + j;
            if (gn >= N) continue;
            float v = acc[i][j];
            if (EPI == 0) {
                v += bias[gn];
                g_tproj[(size_t)gm * G3 + gn] = v;
            } else if (EPI == 1) {
                v += bias[gn];
                const int b = gm >> 8, s = gm & 255;
                if (gn < 512) {
                    const int h = gn >> 7, hd = gn & 127;
                    g_K[(((size_t)(b * HH + h)) * SS + s) * HDD + hd] = v;
                } else {
                    const int n2 = gn - 512;
                    const int h = n2 >> 7, hd = n2 & 127;
                    g_V[(((size_t)(b * HH + h)) * SS + s) * HDD + hd] = v;
                }
            } else if (EPI == 2) {
                if (gn < 512) {
                    g_q[(size_t)gm * DD + gn] = (v + bias[gn]) * 0.088388347648318447f; // 1/sqrt(128)
                } else {
                    const int n2 = gn - 512;
                    g_hg[(size_t)gm * G3 + n2] = v + bias2[n2];
                }
            } else { // EPI == 3
                const int a = act[gm * TFULL + t];
                v += g_bcombo[gn] + g_tproj[(size_t)a * G3 + gn];
                g_xg[(size_t)gm * G3 + gn] = v;
            }
        }
    }
}

// -------------------- NN GEMM for Wcombo = W_c @ Wo (1536x512x512) --------------------
__launch_bounds__(256)
__global__ void gemm_nn_wcombo(const float* __restrict__ A /*gru_w_ih+512, ld 1024*/,
                               const float* __restrict__ Bm /*out_proj_w, ld 512*/) {
    __shared__ float As[64][20];
    __shared__ float Bs[16][68];
    const int bm = blockIdx.y * 64, bn = blockIdx.x * 64;
    const int tid = threadIdx.x;
    const int tx = tid & 15, ty = tid >> 4;
    const int lr = tid >> 2, lk = (tid & 3) << 2;
    float acc[4][4];
#pragma unroll
    for (int i = 0; i < 4; i++)
#pragma unroll
        for (int j = 0; j < 4; j++) acc[i][j] = 0.f;

    const float* Arow = A + (size_t)(bm + lr) * 1024;
    for (int k0 = 0; k0 < 512; k0 += 16) {
        float4 av = *(const float4*)(Arow + k0 + lk);
        *(float4*)&As[lr][lk] = av;
        float4 bv = *(const float4*)(Bm + (size_t)(k0 + ty) * 512 + bn + tx * 4);
        *(float4*)&Bs[ty][tx * 4] = bv;
        __syncthreads();
#pragma unroll
        for (int kk = 0; kk < 16; kk++) {
            float a0 = As[ty * 4 + 0][kk], a1 = As[ty * 4 + 1][kk];
            float a2 = As[ty * 4 + 2][kk], a3 = As[ty * 4 + 3][kk];
            float4 w4 = *(const float4*)&Bs[kk][tx * 4];
            acc[0][0] += a0 * w4.x; acc[0][1] += a0 * w4.y; acc[0][2] += a0 * w4.z; acc[0][3] += a0 * w4.w;
            acc[1][0] += a1 * w4.x; acc[1][1] += a1 * w4.y; acc[1][2] += a1 * w4.z; acc[1][3] += a1 * w4.w;
            acc[2][0] += a2 * w4.x; acc[2][1] += a2 * w4.y; acc[2][2] += a2 * w4.z; acc[2][3] += a2 * w4.w;
            acc[3][0] += a3 * w4.x; acc[3][1] += a3 * w4.y; acc[3][2] += a3 * w4.z; acc[3][3] += a3 * w4.w;
        }
        __syncthreads();
    }
#pragma unroll
    for (int i = 0; i < 4; i++)
#pragma unroll
        for (int j = 0; j < 4; j++)
            g_Wcombo[(size_t)(bm + ty * 4 + i) * 512 + bn + tx * 4 + j] = acc[i][j];
}

// -------------------- per-step attention: scores + softmax + ctx --------------------
// NOTE: mask is read as 4-byte words (int32 or float32 encodings of bool both
// give nonzero words for True), NOT as bytes.
__launch_bounds__(128)
__global__ void attn_kernel(const int* __restrict__ mask) {
    const int bh = blockIdx.x;               // b*HH + h
    const int b = bh >> 2;
    const int h = bh & 3;
    __shared__ float sq[HDD];
    __shared__ float sc[SS];
    __shared__ float red[8];
    const int tid = threadIdx.x, lane = tid & 31, w = tid >> 5;

    sq[tid] = g_q[(size_t)b * DD + h * HDD + tid];
    __syncthreads();
    const float q0 = sq[lane], q1 = sq[lane + 32], q2 = sq[lane + 64], q3 = sq[lane + 96];

    const float* Kb = g_K + (size_t)bh * SS * HDD;
    for (int s = w; s < SS; s += 4) {
        const float* kr = Kb + s * HDD;
        float p = kr[lane] * q0 + kr[lane + 32] * q1 + kr[lane + 64] * q2 + kr[lane + 96] * q3;
#pragma unroll
        for (int o = 16; o > 0; o >>= 1) p += __shfl_xor_sync(0xffffffffu, p, o);
        if (lane == 0) sc[s] = (mask[b * SS + s] != 0) ? p : -3.402823466e38f;
    }
    __syncthreads();

    const float v0 = sc[tid], v1 = sc[tid + 128];
    float lm = fmaxf(v0, v1);
#pragma unroll
    for (int o = 16; o > 0; o >>= 1) lm = fmaxf(lm, __shfl_xor_sync(0xffffffffu, lm, o));
    if (lane == 0) red[w] = lm;
    __syncthreads();
    const float m = fmaxf(fmaxf(red[0], red[1]), fmaxf(red[2], red[3]));
    const float e0 = __expf(v0 - m), e1 = __expf(v1 - m);
    float ls = e0 + e1;
#pragma unroll
    for (int o = 16; o > 0; o >>= 1) ls += __shfl_xor_sync(0xffffffffu, ls, o);
    if (lane == 0) red[4 + w] = ls;
    sc[tid] = e0;
    sc[tid + 128] = e1;
    __syncthreads();
    const float inv = 1.f / (red[4] + red[5] + red[6] + red[7]);

    const float* Vb = g_V + (size_t)bh * SS * HDD;
    float acc = 0.f;
#pragma unroll 8
    for (int s = 0; s < SS; s++) acc += sc[s] * Vb[s * HDD + tid];
    g_ctx[(size_t)b * DD + h * HDD + tid] = acc * inv;
}

// -------------------- per-step GRU gates + hidden update --------------------
__global__ void gates_kernel(int t) {
    const int i = blockIdx.x * blockDim.x + threadIdx.x;   // 0..BB*DD-1
    const int b = i >> 9, d = i & 511;
    const float xr = g_xg[(size_t)b * G3 + d];
    const float xz = g_xg[(size_t)b * G3 + 512 + d];
    const float xn = g_xg[(size_t)b * G3 + 1024 + d];
    const float hr = g_hg[(size_t)b * G3 + d];
    const float hz = g_hg[(size_t)b * G3 + 512 + d];
    const float hn = g_hg[(size_t)b * G3 + 1024 + d];
    const float r = 1.f / (1.f + __expf(-(xr + hr)));
    const float z = 1.f / (1.f + __expf(-(xz + hz)));
    const float n = tanhf(xn + r * hn);
    const float hprev = g_h[i];
    const float hnew = (1.f - z) * n + z * hprev;
    g_h[i] = hnew;
    g_Hseq[(size_t)t * BB * DD + i] = hnew;
}

// -------------------- final: LayerNorm + vocab projection (batched over T*B) --------------------
__launch_bounds__(128)
__global__ void final_kernel(float* __restrict__ out,
                             const float* __restrict__ gamma, const float* __restrict__ beta,
                             const float* __restrict__ ow, const float* __restrict__ ob) {
    const int row = blockIdx.x;          // t*BB + b
    const int t = row >> 8;
    const int b = row & 255;
    const float* x = g_Hseq + (size_t)row * DD;
    __shared__ float sn[DD];
    __shared__ float red[8];
    const int tid = threadIdx.x, lane = tid & 31, w = tid >> 5;

    float s = 0.f;
    for (int d = tid; d < DD; d += 128) { float v = x[d]; sn[d] = v; s += v; }
#pragma unroll
    for (int o = 16; o > 0; o >>= 1) s += __shfl_xor_sync(0xffffffffu, s, o);
    if (lane == 0) red[w] = s;
    __syncthreads();
    const float mu = (red[0] + red[1] + red[2] + red[3]) * (1.f / 512.f);

    float vs = 0.f;
    for (int d = tid; d < DD; d += 128) { float c = sn[d] - mu; vs += c * c; }
#pragma unroll
    for (int o = 16; o > 0; o >>= 1) vs += __shfl_xor_sync(0xffffffffu, vs, o);
    if (lane == 0) red[4 + w] = vs;
    __syncthreads();
    const float var = (red[4] + red[5] + red[6] + red[7]) * (1.f / 512.f);
    const float rs = rsqrtf(var + 1e-5f);

    for (int d = tid; d < DD; d += 128) sn[d] = (sn[d] - mu) * rs * gamma[d] + beta[d];
    __syncthreads();

    for (int v = w; v < VV; v += 4) {
        const float* wr = ow + (size_t)v * DD;
        float p = 0.f;
#pragma unroll
        for (int d = lane; d < DD; d += 32) p += sn[d] * wr[d];
#pragma unroll
        for (int o = 16; o > 0; o >>= 1) p += __shfl_xor_sync(0xffffffffu, p, o);
        if (lane == 0) out[(size_t)b * TT * VV + t * VV + v] = p + ob[v];
    }
}

// -------------------- launch --------------------
extern "C" void kernel_launch(void* const* d_in, const int* in_sizes, int n_in,
                              void* d_out, int out_size) {
    (void)in_sizes; (void)n_in; (void)out_size;
    const float* init_hidden = (const float*)d_in[0];
    const int* act           = (const int*)d_in[1];
    const float* enc_seq     = (const float*)d_in[2];
    const int* enc_mask      = (const int*)d_in[3];   // bool -> 4-byte words
    const float* emb_table   = (const float*)d_in[4];
    const float* in_proj_w   = (const float*)d_in[5];
    const float* in_proj_b   = (const float*)d_in[6];
    const float* out_proj_w  = (const float*)d_in[7];
    const float* out_proj_b  = (const float*)d_in[8];
    const float* gru_w_ih    = (const float*)d_in[9];
    const float* gru_w_hh    = (const float*)d_in[10];
    const float* gru_b_ih    = (const float*)d_in[11];
    const float* gru_b_hh    = (const float*)d_in[12];
    const float* ln_gamma    = (const float*)d_in[13];
    const float* ln_beta     = (const float*)d_in[14];
    const float* out_w       = (const float*)d_in[15];
    const float* out_b       = (const float*)d_in[16];
    float* out = (float*)d_out;

    // one-time (per replay) precompute
    copy_h_kernel<<<512, 256>>>(init_hidden);
    bcombo_kernel<<<G3 / 4, 128>>>(gru_w_ih, out_proj_b);
    // tproj: M=50, N=1536  (A=emb_table ld 512, W=gru_w_ih ld 1024 -> emb columns)
    gemm_tn<0><<<dim3(24, 1), 256>>>(emb_table, 512, gru_w_ih, 1024,
                                     nullptr, 0, 1 << 30, gru_b_ih, nullptr,
                                     50, G3, nullptr, 0);
    // Wcombo = W_c @ Wo
    gemm_nn_wcombo<<<dim3(8, 24), 256>>>(gru_w_ih + 512, out_proj_w);
    // KV: M=B*S=65536, N=1024 (rows [Wk;Wv] of in_proj_w)
    gemm_tn<1><<<dim3(16, 1024), 256>>>(enc_seq, 512, in_proj_w + (size_t)512 * 512, 512,
                                        nullptr, 0, 1 << 30, in_proj_b + 512, nullptr,
                                        BB * SS, 1024, nullptr, 0);

    for (int t = 0; t < TT; t++) {
        // q (scaled) + hg
        gemm_tn<2><<<dim3(32, 4), 256>>>(nullptr, 512, in_proj_w, 512,
                                         gru_w_hh, 512, 512, in_proj_b, gru_b_hh,
                                         BB, 2048, nullptr, 0);
        attn_kernel<<<BB * HH, 128>>>(enc_mask);
        // xg = ctx@Wcombo^T + bcombo + tproj[act[:,t]]
        gemm_tn<3><<<dim3(24, 4), 256>>>(nullptr, 512, nullptr, 512,
                                         nullptr, 0, 1 << 30, nullptr, nullptr,
                                         BB, G3, act, t);
        gates_kernel<<<512, 256>>>(t);
    }

    final_kernel<<<TT * BB, 128>>>(out, ln_gamma, ln_beta, out_w, out_b);
}

// round 3
// speedup vs baseline: 1.0831x; 1.0831x over previous
#include <cuda_runtime.h>
#include <cuda_fp16.h>

#define BB 256
#define TT 127
#define TFULL 128
#define SS 256
#define DD 512
#define VV 50
#define HH 4
#define HDD 128
#define G3 1536

// -------------------- device scratch (no allocations allowed) --------------------
__device__ __align__(128) __half g_K[(size_t)BB * HH * SS * HDD];   // fp16 [b][h][s][hd]
__device__ __align__(128) __half g_V[(size_t)BB * HH * SS * HDD];   // fp16
__device__ __align__(128) __half g_enc_h[(size_t)BB * SS * DD];     // enc_seq fp16
__device__ __align__(128) __half g_Wkv[(size_t)1024 * DD];          // [Wk;Wv] fp16
__device__ __align__(128) float g_h[BB * DD];
__device__ __align__(128) float g_q[BB * DD];        // pre-scaled q
__device__ __align__(128) float g_hg[BB * G3];       // h @ W_hh^T + b_hh
__device__ __align__(128) float g_ctx[BB * DD];
__device__ __align__(128) float g_xg[BB * G3];
__device__ __align__(128) float g_Hseq[(size_t)TT * BB * DD];       // NORMED hidden
__device__ __align__(128) float g_tproj[VV * G3];
__device__ __align__(128) float g_Wcombo[(size_t)G3 * DD];
__device__ __align__(128) float g_bcombo[G3];

// -------------------- small helpers --------------------
__global__ void copy_h_kernel(const float* __restrict__ src) {
    int i = blockIdx.x * blockDim.x + threadIdx.x;
    g_h[i] = src[i];
}

__global__ void bcombo_kernel(const float* __restrict__ wih, const float* __restrict__ bo) {
    int n = blockIdx.x * 4 + (threadIdx.x >> 5);
    int lane = threadIdx.x & 31;
    const float* r = wih + (size_t)n * 1024 + 512;
    float p = 0.f;
    for (int k = lane; k < DD; k += 32) p += r[k] * bo[k];
#pragma unroll
    for (int o = 16; o > 0; o >>= 1) p += __shfl_xor_sync(0xffffffffu, p, o);
    if (lane == 0) g_bcombo[n] = p;
}

// fp32 -> fp16 converters (8 elements / thread, vectorized)
__global__ void conv_enc_kernel(const float* __restrict__ src) {
    size_t i = (size_t)(blockIdx.x * blockDim.x + threadIdx.x) * 8;
    float4 f0 = *(const float4*)(src + i);
    float4 f1 = *(const float4*)(src + i + 4);
    __half2 h0 = __floats2half2_rn(f0.x, f0.y);
    __half2 h1 = __floats2half2_rn(f0.z, f0.w);
    __half2 h2 = __floats2half2_rn(f1.x, f1.y);
    __half2 h3 = __floats2half2_rn(f1.z, f1.w);
    uint4 u = make_uint4(*(unsigned*)&h0, *(unsigned*)&h1, *(unsigned*)&h2, *(unsigned*)&h3);
    *(uint4*)(g_enc_h + i) = u;
}

__global__ void conv_wkv_kernel(const float* __restrict__ src) {
    size_t i = (size_t)(blockIdx.x * blockDim.x + threadIdx.x) * 8;
    float4 f0 = *(const float4*)(src + i);
    float4 f1 = *(const float4*)(src + i + 4);
    __half2 h0 = __floats2half2_rn(f0.x, f0.y);
    __half2 h1 = __floats2half2_rn(f0.z, f0.w);
    __half2 h2 = __floats2half2_rn(f1.x, f1.y);
    __half2 h3 = __floats2half2_rn(f1.z, f1.w);
    uint4 u = make_uint4(*(unsigned*)&h0, *(unsigned*)&h1, *(unsigned*)&h2, *(unsigned*)&h3);
    *(uint4*)(g_Wkv + i) = u;
}

// -------------------- generic fp32 TN GEMM, K=512 fixed --------------------
// EPI 0: tproj   (A=emb_table, W=gru_w_ih ld 1024, +b_ih  -> g_tproj)
// EPI 2: QH      (A=g_h, W=Wq / W2=gru_w_hh split at 512  -> g_q (scaled) / g_hg)
// EPI 3: XG      (A=g_ctx, W=g_Wcombo, + bcombo + tproj[act] -> g_xg)
template <int EPI>
__launch_bounds__(256)
__global__ void gemm_tn(const float* __restrict__ A, int lda,
                        const float* __restrict__ W, int ldw,
                        const float* __restrict__ W2, int ldw2, int nsplit,
                        const float* __restrict__ bias, const float* __restrict__ bias2,
                        int M, int N,
                        const int* __restrict__ act, int t) {
    __shared__ float As[16][68];
    __shared__ float Ws[16][68];
    const int bm = blockIdx.y * 64, bn = blockIdx.x * 64;
    const int tid = threadIdx.x;
    const int tx = tid & 15, ty = tid >> 4;
    const int lr = tid >> 2;
    const int lk = (tid & 3) << 2;

    const float* Abase = A;
    if (EPI == 2) Abase = g_h;
    if (EPI == 3) Abase = g_ctx;
    const float* Wbase = W;
    if (EPI == 3) Wbase = g_Wcombo;

    float acc[4][4];
#pragma unroll
    for (int i = 0; i < 4; i++)
#pragma unroll
        for (int j = 0; j < 4; j++) acc[i][j] = 0.f;

    const int gm_l = bm + lr;
    const int gn_l = bn + lr;
    const float* Arow = (gm_l < M) ? (Abase + (size_t)gm_l * lda) : nullptr;
    const float* Wrow;
    if (gn_l < nsplit) Wrow = Wbase + (size_t)gn_l * ldw;
    else Wrow = W2 + (size_t)(gn_l - nsplit) * ldw2;
    const bool wok = (gn_l < N);

    for (int k0 = 0; k0 < 512; k0 += 16) {
        float4 av = make_float4(0.f, 0.f, 0.f, 0.f);
        if (Arow) av = *(const float4*)(Arow + k0 + lk);
        float4 wv = make_float4(0.f, 0.f, 0.f, 0.f);
        if (wok) wv = *(const float4*)(Wrow + k0 + lk);
        As[lk + 0][lr] = av.x; As[lk + 1][lr] = av.y;
        As[lk + 2][lr] = av.z; As[lk + 3][lr] = av.w;
        Ws[lk + 0][lr] = wv.x; Ws[lk + 1][lr] = wv.y;
        Ws[lk + 2][lr] = wv.z; Ws[lk + 3][lr] = wv.w;
        __syncthreads();
#pragma unroll
        for (int kk = 0; kk < 16; kk++) {
            float4 a4 = *(const float4*)&As[kk][ty * 4];
            float4 w4 = *(const float4*)&Ws[kk][tx * 4];
            acc[0][0] += a4.x * w4.x; acc[0][1] += a4.x * w4.y;
            acc[0][2] += a4.x * w4.z; acc[0][3] += a4.x * w4.w;
            acc[1][0] += a4.y * w4.x; acc[1][1] += a4.y * w4.y;
            acc[1][2] += a4.y * w4.z; acc[1][3] += a4.y * w4.w;
            acc[2][0] += a4.z * w4.x; acc[2][1] += a4.z * w4.y;
            acc[2][2] += a4.z * w4.z; acc[2][3] += a4.z * w4.w;
            acc[3][0] += a4.w * w4.x; acc[3][1] += a4.w * w4.y;
            acc[3][2] += a4.w * w4.z; acc[3][3] += a4.w * w4.w;
        }
        __syncthreads();
    }

#pragma unroll
    for (int i = 0; i < 4; i++) {
        const int gm = bm + ty * 4 + i;
        if (gm >= M) continue;
#pragma unroll
        for (int j = 0; j < 4; j++) {
            const int gn = bn + tx * 4 + j;
            if (gn >= N) continue;
            float v = acc[i][j];
            if (EPI == 0) {
                v += bias[gn];
                g_tproj[(size_t)gm * G3 + gn] = v;
            } else if (EPI == 2) {
                if (gn < 512) {
                    g_q[(size_t)gm * DD + gn] = (v + bias[gn]) * 0.088388347648318447f;
                } else {
                    const int n2 = gn - 512;
                    g_hg[(size_t)gm * G3 + n2] = v + bias2[n2];
                }
            } else { // EPI == 3
                const int a = act[gm * TFULL + t];
                v += g_bcombo[gn] + g_tproj[(size_t)a * G3 + gn];
                g_xg[(size_t)gm * G3 + gn] = v;
            }
        }
    }
}

// -------------------- NN GEMM for Wcombo = W_c @ Wo (1536x512x512) --------------------
__launch_bounds__(256)
__global__ void gemm_nn_wcombo(const float* __restrict__ A,
                               const float* __restrict__ Bm) {
    __shared__ float As[64][20];
    __shared__ float Bs[16][68];
    const int bm = blockIdx.y * 64, bn = blockIdx.x * 64;
    const int tid = threadIdx.x;
    const int tx = tid & 15, ty = tid >> 4;
    const int lr = tid >> 2, lk = (tid & 3) << 2;
    float acc[4][4];
#pragma unroll
    for (int i = 0; i < 4; i++)
#pragma unroll
        for (int j = 0; j < 4; j++) acc[i][j] = 0.f;

    const float* Arow = A + (size_t)(bm + lr) * 1024;
    for (int k0 = 0; k0 < 512; k0 += 16) {
        float4 av = *(const float4*)(Arow + k0 + lk);
        *(float4*)&As[lr][lk] = av;
        float4 bv = *(const float4*)(Bm + (size_t)(k0 + ty) * 512 + bn + tx * 4);
        *(float4*)&Bs[ty][tx * 4] = bv;
        __syncthreads();
#pragma unroll
        for (int kk = 0; kk < 16; kk++) {
            float a0 = As[ty * 4 + 0][kk], a1 = As[ty * 4 + 1][kk];
            float a2 = As[ty * 4 + 2][kk], a3 = As[ty * 4 + 3][kk];
            float4 w4 = *(const float4*)&Bs[kk][tx * 4];
            acc[0][0] += a0 * w4.x; acc[0][1] += a0 * w4.y; acc[0][2] += a0 * w4.z; acc[0][3] += a0 * w4.w;
            acc[1][0] += a1 * w4.x; acc[1][1] += a1 * w4.y; acc[1][2] += a1 * w4.z; acc[1][3] += a1 * w4.w;
            acc[2][0] += a2 * w4.x; acc[2][1] += a2 * w4.y; acc[2][2] += a2 * w4.z; acc[2][3] += a2 * w4.w;
            acc[3][0] += a3 * w4.x; acc[3][1] += a3 * w4.y; acc[3][2] += a3 * w4.z; acc[3][3] += a3 * w4.w;
        }
        __syncthreads();
    }
#pragma unroll
    for (int i = 0; i < 4; i++)
#pragma unroll
        for (int j = 0; j < 4; j++)
            g_Wcombo[(size_t)(bm + ty * 4 + i) * 512 + bn + tx * 4 + j] = acc[i][j];
}

// -------------------- KV precompute: fp16 tensor-core GEMM --------------------
// C[m][n] = sum_k enc_h[m][k] * Wkv[n][k], m in [0,65536), n in [0,1024), K=512.
// mma.sync.m16n8k16 f32.f16.f16.f32, fragments loaded directly from padded smem.
__device__ __forceinline__ void mma16816(float* d, unsigned a0, unsigned a1, unsigned a2,
                                         unsigned a3, unsigned b0, unsigned b1) {
    asm volatile(
        "mma.sync.aligned.m16n8k16.row.col.f32.f16.f16.f32 "
        "{%0,%1,%2,%3}, {%4,%5,%6,%7}, {%8,%9}, {%0,%1,%2,%3};\n"
        : "+f"(d[0]), "+f"(d[1]), "+f"(d[2]), "+f"(d[3])
        : "r"(a0), "r"(a1), "r"(a2), "r"(a3), "r"(b0), "r"(b1));
}

__launch_bounds__(128)
__global__ void hmma_kv_kernel(const float* __restrict__ bias /* in_proj_b+512 */) {
    __shared__ __half As[64][72];   // row stride 144B (16B-aligned, conflict-free frags)
    __shared__ __half Bs[64][72];
    const int bm = blockIdx.y * 64, bn = blockIdx.x * 64;
    const int tid = threadIdx.x, lane = tid & 31, w = tid >> 5;
    const int gr = lane >> 2, q2 = (lane & 3) * 2;
    const int wm = (w >> 1) * 32, wn = (w & 1) * 32;
    const int lr = tid >> 1, lc = (tid & 1) * 32;   // gmem->smem: row, 32-half segment

    float acc[2][4][4];
#pragma unroll
    for (int mi = 0; mi < 2; mi++)
#pragma unroll
        for (int nj = 0; nj < 4; nj++)
#pragma unroll
            for (int r = 0; r < 4; r++) acc[mi][nj][r] = 0.f;

    for (int kt = 0; kt < 512; kt += 64) {
        const uint4* ag = (const uint4*)(g_enc_h + (size_t)(bm + lr) * 512 + kt + lc);
        const uint4* bg = (const uint4*)(g_Wkv + (size_t)(bn + lr) * 512 + kt + lc);
        uint4 a0v = ag[0], a1v = ag[1], a2v = ag[2], a3v = ag[3];
        uint4 b0v = bg[0], b1v = bg[1], b2v = bg[2], b3v = bg[3];
        __syncthreads();
        *(uint4*)&As[lr][lc + 0]  = a0v; *(uint4*)&As[lr][lc + 8]  = a1v;
        *(uint4*)&As[lr][lc + 16] = a2v; *(uint4*)&As[lr][lc + 24] = a3v;
        *(uint4*)&Bs[lr][lc + 0]  = b0v; *(uint4*)&Bs[lr][lc + 8]  = b1v;
        *(uint4*)&Bs[lr][lc + 16] = b2v; *(uint4*)&Bs[lr][lc + 24] = b3v;
        __syncthreads();
#pragma unroll
        for (int ks = 0; ks < 4; ks++) {
            const int kk = ks * 16;
            unsigned b0[4], b1[4];
#pragma unroll
            for (int nj = 0; nj < 4; nj++) {
                const int n = wn + nj * 8 + gr;
                b0[nj] = *(const unsigned*)&Bs[n][kk + q2];
                b1[nj] = *(const unsigned*)&Bs[n][kk + q2 + 8];
            }
#pragma unroll
            for (int mi = 0; mi < 2; mi++) {
                const int rm = wm + mi * 16;
                unsigned a0 = *(const unsigned*)&As[rm + gr][kk + q2];
                unsigned a1 = *(const unsigned*)&As[rm + gr + 8][kk + q2];
                unsigned a2 = *(const unsigned*)&As[rm + gr][kk + q2 + 8];
                unsigned a3 = *(const unsigned*)&As[rm + gr + 8][kk + q2 + 8];
#pragma unroll
                for (int nj = 0; nj < 4; nj++)
                    mma16816(acc[mi][nj], a0, a1, a2, a3, b0[nj], b1[nj]);
            }
        }
    }

    // epilogue: +bias, scatter to g_K / g_V fp16 [b][h][s][hd]
#pragma unroll
    for (int mi = 0; mi < 2; mi++) {
#pragma unroll
        for (int nj = 0; nj < 4; nj++) {
            const int n0 = bn + wn + nj * 8 + q2;
            const float bi0 = bias[n0], bi1 = bias[n0 + 1];
#pragma unroll
            for (int half_row = 0; half_row < 2; half_row++) {
                const int m = bm + wm + mi * 16 + gr + half_row * 8;
                const float v0 = acc[mi][nj][half_row * 2 + 0] + bi0;
                const float v1 = acc[mi][nj][half_row * 2 + 1] + bi1;
                const int b = m >> 8, s = m & 255;
                __half* dst; int nn;
                if (n0 < 512) { dst = g_K; nn = n0; }
                else          { dst = g_V; nn = n0 - 512; }
                const int h = nn >> 7, hd = nn & 127;
                __half2 hv = __floats2half2_rn(v0, v1);
                *(__half2*)(dst + (((size_t)(b * HH + h) * SS + s) * HDD + hd)) = hv;
            }
        }
    }
}

// -------------------- per-step attention (fp16 K/V) --------------------
__launch_bounds__(128)
__global__ void attn_kernel(const int* __restrict__ mask) {
    const int bh = blockIdx.x;
    const int b = bh >> 2;
    const int h = bh & 3;
    __shared__ float sq[HDD];
    __shared__ float sc[SS];
    __shared__ float red[8];
    const int tid = threadIdx.x, lane = tid & 31, w = tid >> 5;

    sq[tid] = g_q[(size_t)b * DD + h * HDD + tid];
    __syncthreads();
    const float q0 = sq[2 * lane], q1 = sq[2 * lane + 1];
    const float q2 = sq[64 + 2 * lane], q3 = sq[65 + 2 * lane];

    const __half2* Kb2 = (const __half2*)(g_K + (size_t)bh * SS * HDD);
    for (int s = w; s < SS; s += 4) {
        const __half2 k1 = Kb2[s * 64 + lane];
        const __half2 k2 = Kb2[s * 64 + 32 + lane];
        const float2 f1 = __half22float2(k1), f2 = __half22float2(k2);
        float p = f1.x * q0 + f1.y * q1 + f2.x * q2 + f2.y * q3;
#pragma unroll
        for (int o = 16; o > 0; o >>= 1) p += __shfl_xor_sync(0xffffffffu, p, o);
        if (lane == 0) sc[s] = (mask[b * SS + s] != 0) ? p : -3.402823466e38f;
    }
    __syncthreads();

    const float v0 = sc[tid], v1 = sc[tid + 128];
    float lm = fmaxf(v0, v1);
#pragma unroll
    for (int o = 16; o > 0; o >>= 1) lm = fmaxf(lm, __shfl_xor_sync(0xffffffffu, lm, o));
    if (lane == 0) red[w] = lm;
    __syncthreads();
    const float m = fmaxf(fmaxf(red[0], red[1]), fmaxf(red[2], red[3]));
    const float e0 = __expf(v0 - m), e1 = __expf(v1 - m);
    float ls = e0 + e1;
#pragma unroll
    for (int o = 16; o > 0; o >>= 1) ls += __shfl_xor_sync(0xffffffffu, ls, o);
    if (lane == 0) red[4 + w] = ls;
    sc[tid] = e0;
    sc[tid + 128] = e1;
    __syncthreads();
    const float inv = 1.f / (red[4] + red[5] + red[6] + red[7]);

    const __half* Vb = g_V + (size_t)bh * SS * HDD;
    float acc = 0.f;
#pragma unroll 8
    for (int s = 0; s < SS; s++) acc += sc[s] * __half2float(Vb[s * HDD + tid]);
    g_ctx[(size_t)b * DD + h * HDD + tid] = acc * inv;
}

// -------------------- per-step GRU gates + hidden update + fused LayerNorm --------------------
__launch_bounds__(512)
__global__ void gates_ln_kernel(int t, const float* __restrict__ gamma,
                                const float* __restrict__ beta) {
    const int b = blockIdx.x;      // 256 blocks
    const int d = threadIdx.x;     // 512 threads
    const int lane = d & 31, w = d >> 5;
    __shared__ float red[32];
    __shared__ float bcast[2];

    const float xr = g_xg[(size_t)b * G3 + d];
    const float xz = g_xg[(size_t)b * G3 + 512 + d];
    const float xn = g_xg[(size_t)b * G3 + 1024 + d];
    const float hr = g_hg[(size_t)b * G3 + d];
    const float hz = g_hg[(size_t)b * G3 + 512 + d];
    const float hn = g_hg[(size_t)b * G3 + 1024 + d];
    const float r = 1.f / (1.f + __expf(-(xr + hr)));
    const float z = 1.f / (1.f + __expf(-(xz + hz)));
    const float n = tanhf(xn + r * hn);
    const float hprev = g_h[b * DD + d];
    const float hnew = (1.f - z) * n + z * hprev;
    g_h[b * DD + d] = hnew;

    // block LN: sum + sumsq in one pass
    float s1 = hnew, s2 = hnew * hnew;
#pragma unroll
    for (int o = 16; o > 0; o >>= 1) {
        s1 += __shfl_xor_sync(0xffffffffu, s1, o);
        s2 += __shfl_xor_sync(0xffffffffu, s2, o);
    }
    if (lane == 0) { red[w] = s1; red[16 + w] = s2; }
    __syncthreads();
    if (w == 0) {
        float a = (lane < 16) ? red[lane] : 0.f;
        float c = (lane < 16) ? red[16 + lane] : 0.f;
#pragma unroll
        for (int o = 8; o > 0; o >>= 1) {
            a += __shfl_xor_sync(0xffffffffu, a, o);
            c += __shfl_xor_sync(0xffffffffu, c, o);
        }
        if (lane == 0) { bcast[0] = a * (1.f / 512.f); bcast[1] = c * (1.f / 512.f); }
    }
    __syncthreads();
    const float mu = bcast[0];
    const float var = bcast[1] - mu * mu;
    const float rs = rsqrtf(var + 1e-5f);
    g_Hseq[((size_t)t * BB + b) * DD + d] = (hnew - mu) * rs * gamma[d] + beta[d];
}

// -------------------- final: logits GEMM over normed hidden --------------------
__launch_bounds__(512)
__global__ void final_logits_kernel(float* __restrict__ out,
                                    const float* __restrict__ ow,
                                    const float* __restrict__ ob) {
    const int tid = threadIdx.x;
    const int r = blockIdx.x * 8 + (tid & 7);    // row in [0, TT*BB)
    const int v = tid >> 3;                      // 0..63
    if (v >= VV) return;
    const float* x = g_Hseq + (size_t)r * DD;
    const float* wr = ow + (size_t)v * DD;
    float acc = 0.f;
#pragma unroll 8
    for (int dd = 0; dd < DD; dd += 4) {
        float4 xv = *(const float4*)(x + dd);
        float4 wv = *(const float4*)(wr + dd);
        acc += xv.x * wv.x + xv.y * wv.y + xv.z * wv.z + xv.w * wv.w;
    }
    const int t = r >> 8, b = r & 255;
    out[(size_t)b * (TT * VV) + t * VV + v] = acc + ob[v];
}

// -------------------- launch --------------------
extern "C" void kernel_launch(void* const* d_in, const int* in_sizes, int n_in,
                              void* d_out, int out_size) {
    (void)in_sizes; (void)n_in; (void)out_size;
    const float* init_hidden = (const float*)d_in[0];
    const int* act           = (const int*)d_in[1];
    const float* enc_seq     = (const float*)d_in[2];
    const int* enc_mask      = (const int*)d_in[3];
    const float* emb_table   = (const float*)d_in[4];
    const float* in_proj_w   = (const float*)d_in[5];
    const float* in_proj_b   = (const float*)d_in[6];
    const float* out_proj_w  = (const float*)d_in[7];
    const float* out_proj_b  = (const float*)d_in[8];
    const float* gru_w_ih    = (const float*)d_in[9];
    const float* gru_w_hh    = (const float*)d_in[10];
    const float* gru_b_ih    = (const float*)d_in[11];
    const float* gru_b_hh    = (const float*)d_in[12];
    const float* ln_gamma    = (const float*)d_in[13];
    const float* ln_beta     = (const float*)d_in[14];
    const float* out_w       = (const float*)d_in[15];
    const float* out_b       = (const float*)d_in[16];
    float* out = (float*)d_out;

    // ---- one-time precompute ----
    copy_h_kernel<<<512, 256>>>(init_hidden);
    bcombo_kernel<<<G3 / 4, 128>>>(gru_w_ih, out_proj_b);
    conv_enc_kernel<<<(BB * SS * DD) / 8 / 256, 256>>>(enc_seq);
    conv_wkv_kernel<<<(1024 * DD) / 8 / 256, 256>>>(in_proj_w + (size_t)512 * 512);
    gemm_tn<0><<<dim3(24, 1), 256>>>(emb_table, 512, gru_w_ih, 1024,
                                     nullptr, 0, 1 << 30, gru_b_ih, nullptr,
                                     50, G3, nullptr, 0);
    gemm_nn_wcombo<<<dim3(8, 24), 256>>>(gru_w_ih + 512, out_proj_w);
    // KV: tensor-core fp16 GEMM, M=65536, N=1024, K=512
    hmma_kv_kernel<<<dim3(16, 1024), 128>>>(in_proj_b + 512);

    // ---- 127 serial steps ----
    for (int t = 0; t < TT; t++) {
        gemm_tn<2><<<dim3(32, 4), 256>>>(nullptr, 512, in_proj_w, 512,
                                         gru_w_hh, 512, 512, in_proj_b, gru_b_hh,
                                         BB, 2048, nullptr, 0);
        attn_kernel<<<BB * HH, 128>>>(enc_mask);
        gemm_tn<3><<<dim3(24, 4), 256>>>(nullptr, 512, nullptr, 512,
                                         nullptr, 0, 1 << 30, nullptr, nullptr,
                                         BB, G3, act, t);
        gates_ln_kernel<<<BB, 512>>>(t, ln_gamma, ln_beta);
    }

    // ---- final logits ----
    final_logits_kernel<<<(TT * BB) / 8, 512>>>(out, out_w, out_b);
}

// round 4
// speedup vs baseline: 1.5277x; 1.4105x over previous
#include <cuda_runtime.h>
#include <cuda_fp16.h>

#define BB 256
#define TT 127
#define TFULL 128
#define SS 256
#define DD 512
#define VV 50
#define HH 4
#define HDD 128
#define G3 1536

// -------------------- device scratch (no allocations allowed) --------------------
__device__ __align__(128) __half g_K[(size_t)BB * HH * SS * HDD];   // fp16 [b][h][s][hd]
__device__ __align__(128) __half g_V[(size_t)BB * HH * SS * HDD];   // fp16
__device__ __align__(128) __half g_enc_h[(size_t)BB * SS * DD];     // enc_seq fp16
__device__ __align__(128) __half g_Wkv[(size_t)1024 * DD];          // [Wk;Wv] fp16
__device__ __align__(128) __half g_Wqh16[(size_t)2048 * DD];        // [Wq; W_hh] fp16
__device__ __align__(128) __half g_Wc16[(size_t)G3 * DD];           // Wcombo fp16
__device__ __align__(128) __half g_h16[BB * DD];                    // fp16 copy of h
__device__ __align__(128) __half g_ctx16[BB * DD];                  // fp16 ctx
__device__ __align__(128) float g_h[BB * DD];
__device__ __align__(128) float g_q[BB * DD];        // pre-scaled q
__device__ __align__(128) float g_hg[BB * G3];       // h @ W_hh^T + b_hh
__device__ __align__(128) float g_xg[BB * G3];
__device__ __align__(128) float g_Hseq[(size_t)TT * BB * DD];       // NORMED hidden
__device__ __align__(128) float g_tproj[VV * G3];
__device__ __align__(128) float g_Wcombo[(size_t)G3 * DD];
__device__ __align__(128) float g_bcombo[G3];

// -------------------- small helpers --------------------
__global__ void copy_h_kernel(const float* __restrict__ src) {
    int i = blockIdx.x * blockDim.x + threadIdx.x;
    float v = src[i];
    g_h[i] = v;
    g_h16[i] = __float2half(v);
}

__global__ void bcombo_kernel(const float* __restrict__ wih, const float* __restrict__ bo) {
    int n = blockIdx.x * 4 + (threadIdx.x >> 5);
    int lane = threadIdx.x & 31;
    const float* r = wih + (size_t)n * 1024 + 512;
    float p = 0.f;
    for (int k = lane; k < DD; k += 32) p += r[k] * bo[k];
#pragma unroll
    for (int o = 16; o > 0; o >>= 1) p += __shfl_xor_sync(0xffffffffu, p, o);
    if (lane == 0) g_bcombo[n] = p;
}

// fp32 -> fp16 converters (8 elements / thread, vectorized)
__device__ __forceinline__ uint4 cvt8(const float* src) {
    float4 f0 = *(const float4*)(src);
    float4 f1 = *(const float4*)(src + 4);
    __half2 h0 = __floats2half2_rn(f0.x, f0.y);
    __half2 h1 = __floats2half2_rn(f0.z, f0.w);
    __half2 h2 = __floats2half2_rn(f1.x, f1.y);
    __half2 h3 = __floats2half2_rn(f1.z, f1.w);
    return make_uint4(*(unsigned*)&h0, *(unsigned*)&h1, *(unsigned*)&h2, *(unsigned*)&h3);
}

__global__ void conv_enc_kernel(const float* __restrict__ src) {
    size_t i = (size_t)(blockIdx.x * blockDim.x + threadIdx.x) * 8;
    *(uint4*)(g_enc_h + i) = cvt8(src + i);
}

__global__ void conv_wkv_kernel(const float* __restrict__ src) {
    size_t i = (size_t)(blockIdx.x * blockDim.x + threadIdx.x) * 8;
    *(uint4*)(g_Wkv + i) = cvt8(src + i);
}

// [Wq (512 rows of in_proj_w); W_hh (1536 rows)] -> g_Wqh16
__global__ void conv_wqh_kernel(const float* __restrict__ inproj,
                                const float* __restrict__ whh) {
    size_t i8 = (size_t)(blockIdx.x * blockDim.x + threadIdx.x);
    size_t n = i8 >> 6;                 // row (ld 512 = 64 groups of 8)
    size_t k = (i8 & 63) * 8;
    const float* src = (n < 512) ? (inproj + n * 512 + k) : (whh + (n - 512) * 512 + k);
    *(uint4*)(g_Wqh16 + n * 512 + k) = cvt8(src);
}

__global__ void conv_wc_kernel() {
    size_t i = (size_t)(blockIdx.x * blockDim.x + threadIdx.x) * 8;
    *(uint4*)(g_Wc16 + i) = cvt8(g_Wcombo + i);
}

// -------------------- generic fp32 TN GEMM (precompute only) --------------------
// EPI 0: tproj (A=emb_table, W=gru_w_ih ld 1024, +b_ih -> g_tproj)
template <int EPI>
__launch_bounds__(256)
__global__ void gemm_tn(const float* __restrict__ A, int lda,
                        const float* __restrict__ W, int ldw,
                        const float* __restrict__ bias,
                        int M, int N) {
    __shared__ float As[16][68];
    __shared__ float Ws[16][68];
    const int bm = blockIdx.y * 64, bn = blockIdx.x * 64;
    const int tid = threadIdx.x;
    const int tx = tid & 15, ty = tid >> 4;
    const int lr = tid >> 2;
    const int lk = (tid & 3) << 2;

    float acc[4][4];
#pragma unroll
    for (int i = 0; i < 4; i++)
#pragma unroll
        for (int j = 0; j < 4; j++) acc[i][j] = 0.f;

    const int gm_l = bm + lr;
    const int gn_l = bn + lr;
    const float* Arow = (gm_l < M) ? (A + (size_t)gm_l * lda) : nullptr;
    const float* Wrow = W + (size_t)gn_l * ldw;
    const bool wok = (gn_l < N);

    for (int k0 = 0; k0 < 512; k0 += 16) {
        float4 av = make_float4(0.f, 0.f, 0.f, 0.f);
        if (Arow) av = *(const float4*)(Arow + k0 + lk);
        float4 wv = make_float4(0.f, 0.f, 0.f, 0.f);
        if (wok) wv = *(const float4*)(Wrow + k0 + lk);
        As[lk + 0][lr] = av.x; As[lk + 1][lr] = av.y;
        As[lk + 2][lr] = av.z; As[lk + 3][lr] = av.w;
        Ws[lk + 0][lr] = wv.x; Ws[lk + 1][lr] = wv.y;
        Ws[lk + 2][lr] = wv.z; Ws[lk + 3][lr] = wv.w;
        __syncthreads();
#pragma unroll
        for (int kk = 0; kk < 16; kk++) {
            float4 a4 = *(const float4*)&As[kk][ty * 4];
            float4 w4 = *(const float4*)&Ws[kk][tx * 4];
            acc[0][0] += a4.x * w4.x; acc[0][1] += a4.x * w4.y;
            acc[0][2] += a4.x * w4.z; acc[0][3] += a4.x * w4.w;
            acc[1][0] += a4.y * w4.x; acc[1][1] += a4.y * w4.y;
            acc[1][2] += a4.y * w4.z; acc[1][3] += a4.y * w4.w;
            acc[2][0] += a4.z * w4.x; acc[2][1] += a4.z * w4.y;
            acc[2][2] += a4.z * w4.z; acc[2][3] += a4.z * w4.w;
            acc[3][0] += a4.w * w4.x; acc[3][1] += a4.w * w4.y;
            acc[3][2] += a4.w * w4.z; acc[3][3] += a4.w * w4.w;
        }
        __syncthreads();
    }

#pragma unroll
    for (int i = 0; i < 4; i++) {
        const int gm = bm + ty * 4 + i;
        if (gm >= M) continue;
#pragma unroll
        for (int j = 0; j < 4; j++) {
            const int gn = bn + tx * 4 + j;
            if (gn >= N) continue;
            g_tproj[(size_t)gm * G3 + gn] = acc[i][j] + bias[gn];
        }
    }
}

// -------------------- NN GEMM for Wcombo = W_c @ Wo (1536x512x512) --------------------
__launch_bounds__(256)
__global__ void gemm_nn_wcombo(const float* __restrict__ A,
                               const float* __restrict__ Bm) {
    __shared__ float As[64][20];
    __shared__ float Bs[16][68];
    const int bm = blockIdx.y * 64, bn = blockIdx.x * 64;
    const int tid = threadIdx.x;
    const int tx = tid & 15, ty = tid >> 4;
    const int lr = tid >> 2, lk = (tid & 3) << 2;
    float acc[4][4];
#pragma unroll
    for (int i = 0; i < 4; i++)
#pragma unroll
        for (int j = 0; j < 4; j++) acc[i][j] = 0.f;

    const float* Arow = A + (size_t)(bm + lr) * 1024;
    for (int k0 = 0; k0 < 512; k0 += 16) {
        float4 av = *(const float4*)(Arow + k0 + lk);
        *(float4*)&As[lr][lk] = av;
        float4 bv = *(const float4*)(Bm + (size_t)(k0 + ty) * 512 + bn + tx * 4);
        *(float4*)&Bs[ty][tx * 4] = bv;
        __syncthreads();
#pragma unroll
        for (int kk = 0; kk < 16; kk++) {
            float a0 = As[ty * 4 + 0][kk], a1 = As[ty * 4 + 1][kk];
            float a2 = As[ty * 4 + 2][kk], a3 = As[ty * 4 + 3][kk];
            float4 w4 = *(const float4*)&Bs[kk][tx * 4];
            acc[0][0] += a0 * w4.x; acc[0][1] += a0 * w4.y; acc[0][2] += a0 * w4.z; acc[0][3] += a0 * w4.w;
            acc[1][0] += a1 * w4.x; acc[1][1] += a1 * w4.y; acc[1][2] += a1 * w4.z; acc[1][3] += a1 * w4.w;
            acc[2][0] += a2 * w4.x; acc[2][1] += a2 * w4.y; acc[2][2] += a2 * w4.z; acc[2][3] += a2 * w4.w;
            acc[3][0] += a3 * w4.x; acc[3][1] += a3 * w4.y; acc[3][2] += a3 * w4.z; acc[3][3] += a3 * w4.w;
        }
        __syncthreads();
    }
#pragma unroll
    for (int i = 0; i < 4; i++)
#pragma unroll
        for (int j = 0; j < 4; j++)
            g_Wcombo[(size_t)(bm + ty * 4 + i) * 512 + bn + tx * 4 + j] = acc[i][j];
}

// -------------------- fp16 tensor-core MMA helper --------------------
__device__ __forceinline__ void mma16816(float* d, unsigned a0, unsigned a1, unsigned a2,
                                         unsigned a3, unsigned b0, unsigned b1) {
    asm volatile(
        "mma.sync.aligned.m16n8k16.row.col.f32.f16.f16.f32 "
        "{%0,%1,%2,%3}, {%4,%5,%6,%7}, {%8,%9}, {%0,%1,%2,%3};\n"
        : "+f"(d[0]), "+f"(d[1]), "+f"(d[2]), "+f"(d[3])
        : "r"(a0), "r"(a1), "r"(a2), "r"(a3), "r"(b0), "r"(b1));
}

// -------------------- KV precompute: fp16 tensor-core GEMM --------------------
__launch_bounds__(128)
__global__ void hmma_kv_kernel(const float* __restrict__ bias /* in_proj_b+512 */) {
    __shared__ __half As[64][72];
    __shared__ __half Bs[64][72];
    const int bm = blockIdx.y * 64, bn = blockIdx.x * 64;
    const int tid = threadIdx.x, lane = tid & 31, w = tid >> 5;
    const int gr = lane >> 2, q2 = (lane & 3) * 2;
    const int wm = (w >> 1) * 32, wn = (w & 1) * 32;
    const int lr = tid >> 1, lc = (tid & 1) * 32;

    float acc[2][4][4];
#pragma unroll
    for (int mi = 0; mi < 2; mi++)
#pragma unroll
        for (int nj = 0; nj < 4; nj++)
#pragma unroll
            for (int r = 0; r < 4; r++) acc[mi][nj][r] = 0.f;

    for (int kt = 0; kt < 512; kt += 64) {
        const uint4* ag = (const uint4*)(g_enc_h + (size_t)(bm + lr) * 512 + kt + lc);
        const uint4* bg = (const uint4*)(g_Wkv + (size_t)(bn + lr) * 512 + kt + lc);
        uint4 a0v = ag[0], a1v = ag[1], a2v = ag[2], a3v = ag[3];
        uint4 b0v = bg[0], b1v = bg[1], b2v = bg[2], b3v = bg[3];
        __syncthreads();
        *(uint4*)&As[lr][lc + 0]  = a0v; *(uint4*)&As[lr][lc + 8]  = a1v;
        *(uint4*)&As[lr][lc + 16] = a2v; *(uint4*)&As[lr][lc + 24] = a3v;
        *(uint4*)&Bs[lr][lc + 0]  = b0v; *(uint4*)&Bs[lr][lc + 8]  = b1v;
        *(uint4*)&Bs[lr][lc + 16] = b2v; *(uint4*)&Bs[lr][lc + 24] = b3v;
        __syncthreads();
#pragma unroll
        for (int ks = 0; ks < 4; ks++) {
            const int kk = ks * 16;
            unsigned b0[4], b1[4];
#pragma unroll
            for (int nj = 0; nj < 4; nj++) {
                const int n = wn + nj * 8 + gr;
                b0[nj] = *(const unsigned*)&Bs[n][kk + q2];
                b1[nj] = *(const unsigned*)&Bs[n][kk + q2 + 8];
            }
#pragma unroll
            for (int mi = 0; mi < 2; mi++) {
                const int rm = wm + mi * 16;
                unsigned a0 = *(const unsigned*)&As[rm + gr][kk + q2];
                unsigned a1 = *(const unsigned*)&As[rm + gr + 8][kk + q2];
                unsigned a2 = *(const unsigned*)&As[rm + gr][kk + q2 + 8];
                unsigned a3 = *(const unsigned*)&As[rm + gr + 8][kk + q2 + 8];
#pragma unroll
                for (int nj = 0; nj < 4; nj++)
                    mma16816(acc[mi][nj], a0, a1, a2, a3, b0[nj], b1[nj]);
            }
        }
    }

#pragma unroll
    for (int mi = 0; mi < 2; mi++) {
#pragma unroll
        for (int nj = 0; nj < 4; nj++) {
            const int n0 = bn + wn + nj * 8 + q2;
            const float bi0 = bias[n0], bi1 = bias[n0 + 1];
#pragma unroll
            for (int half_row = 0; half_row < 2; half_row++) {
                const int m = bm + wm + mi * 16 + gr + half_row * 8;
                const float v0 = acc[mi][nj][half_row * 2 + 0] + bi0;
                const float v1 = acc[mi][nj][half_row * 2 + 1] + bi1;
                const int b = m >> 8, s = m & 255;
                __half* dst; int nn;
                if (n0 < 512) { dst = g_K; nn = n0; }
                else          { dst = g_V; nn = n0 - 512; }
                const int h = nn >> 7, hd = nn & 127;
                __half2 hv = __floats2half2_rn(v0, v1);
                *(__half2*)(dst + (((size_t)(b * HH + h) * SS + s) * HDD + hd)) = hv;
            }
        }
    }
}

// -------------------- per-step fp16 GEMMs (tensor core) --------------------
// EPI 0: QH  A=g_h16,  W=g_Wqh16, N=2048: n<512 -> g_q (+bq, scaled); else g_hg (+b_hh)
// EPI 1: XG  A=g_ctx16, W=g_Wc16, N=1536: g_xg = v + bcombo + tproj[act]
template <int EPI>
__launch_bounds__(128)
__global__ void hmma_step(const float* __restrict__ bias,
                          const float* __restrict__ bias2,
                          const int* __restrict__ act, int t) {
    __shared__ __half As[64][72];
    __shared__ __half Bs[64][72];
    const __half* A = (EPI == 0) ? g_h16 : g_ctx16;
    const __half* W = (EPI == 0) ? g_Wqh16 : g_Wc16;
    const int bm = blockIdx.y * 64, bn = blockIdx.x * 64;
    const int tid = threadIdx.x, lane = tid & 31, w = tid >> 5;
    const int gr = lane >> 2, q2 = (lane & 3) * 2;
    const int wm = (w >> 1) * 32, wn = (w & 1) * 32;
    const int lr = tid >> 1, lc = (tid & 1) * 32;

    float acc[2][4][4];
#pragma unroll
    for (int mi = 0; mi < 2; mi++)
#pragma unroll
        for (int nj = 0; nj < 4; nj++)
#pragma unroll
            for (int r = 0; r < 4; r++) acc[mi][nj][r] = 0.f;

    for (int kt = 0; kt < 512; kt += 64) {
        const uint4* ag = (const uint4*)(A + (size_t)(bm + lr) * 512 + kt + lc);
        const uint4* bg = (const uint4*)(W + (size_t)(bn + lr) * 512 + kt + lc);
        uint4 a0v = ag[0], a1v = ag[1], a2v = ag[2], a3v = ag[3];
        uint4 b0v = bg[0], b1v = bg[1], b2v = bg[2], b3v = bg[3];
        __syncthreads();
        *(uint4*)&As[lr][lc + 0]  = a0v; *(uint4*)&As[lr][lc + 8]  = a1v;
        *(uint4*)&As[lr][lc + 16] = a2v; *(uint4*)&As[lr][lc + 24] = a3v;
        *(uint4*)&Bs[lr][lc + 0]  = b0v; *(uint4*)&Bs[lr][lc + 8]  = b1v;
        *(uint4*)&Bs[lr][lc + 16] = b2v; *(uint4*)&Bs[lr][lc + 24] = b3v;
        __syncthreads();
#pragma unroll
        for (int ks = 0; ks < 4; ks++) {
            const int kk = ks * 16;
            unsigned b0[4], b1[4];
#pragma unroll
            for (int nj = 0; nj < 4; nj++) {
                const int n = wn + nj * 8 + gr;
                b0[nj] = *(const unsigned*)&Bs[n][kk + q2];
                b1[nj] = *(const unsigned*)&Bs[n][kk + q2 + 8];
            }
#pragma unroll
            for (int mi = 0; mi < 2; mi++) {
                const int rm = wm + mi * 16;
                unsigned a0 = *(const unsigned*)&As[rm + gr][kk + q2];
                unsigned a1 = *(const unsigned*)&As[rm + gr + 8][kk + q2];
                unsigned a2 = *(const unsigned*)&As[rm + gr][kk + q2 + 8];
                unsigned a3 = *(const unsigned*)&As[rm + gr + 8][kk + q2 + 8];
#pragma unroll
                for (int nj = 0; nj < 4; nj++)
                    mma16816(acc[mi][nj], a0, a1, a2, a3, b0[nj], b1[nj]);
            }
        }
    }

#pragma unroll
    for (int mi = 0; mi < 2; mi++) {
#pragma unroll
        for (int nj = 0; nj < 4; nj++) {
            const int n0 = bn + wn + nj * 8 + q2;
#pragma unroll
            for (int half_row = 0; half_row < 2; half_row++) {
                const int m = bm + wm + mi * 16 + gr + half_row * 8;
                const float v0 = acc[mi][nj][half_row * 2 + 0];
                const float v1 = acc[mi][nj][half_row * 2 + 1];
                if (EPI == 0) {
                    if (n0 < 512) {
                        float2 o;
                        o.x = (v0 + bias[n0]) * 0.088388347648318447f;
                        o.y = (v1 + bias[n0 + 1]) * 0.088388347648318447f;
                        *(float2*)(g_q + (size_t)m * DD + n0) = o;
                    } else {
                        const int nn = n0 - 512;
                        float2 o;
                        o.x = v0 + bias2[nn];
                        o.y = v1 + bias2[nn + 1];
                        *(float2*)(g_hg + (size_t)m * G3 + nn) = o;
                    }
                } else {
                    const int a = act[m * TFULL + t];
                    float2 o;
                    o.x = v0 + g_bcombo[n0] + g_tproj[(size_t)a * G3 + n0];
                    o.y = v1 + g_bcombo[n0 + 1] + g_tproj[(size_t)a * G3 + n0 + 1];
                    *(float2*)(g_xg + (size_t)m * G3 + n0) = o;
                }
            }
        }
    }
}

// -------------------- per-step attention (fp16 K/V, fp16 ctx out) --------------------
__launch_bounds__(128)
__global__ void attn_kernel(const int* __restrict__ mask) {
    const int bh = blockIdx.x;
    const int b = bh >> 2;
    const int h = bh & 3;
    __shared__ float sq[HDD];
    __shared__ float sc[SS];
    __shared__ float red[8];
    const int tid = threadIdx.x, lane = tid & 31, w = tid >> 5;

    sq[tid] = g_q[(size_t)b * DD + h * HDD + tid];
    __syncthreads();
    const float q0 = sq[2 * lane], q1 = sq[2 * lane + 1];
    const float q2 = sq[64 + 2 * lane], q3 = sq[65 + 2 * lane];

    const __half2* Kb2 = (const __half2*)(g_K + (size_t)bh * SS * HDD);
    for (int s = w; s < SS; s += 4) {
        const __half2 k1 = Kb2[s * 64 + lane];
        const __half2 k2 = Kb2[s * 64 + 32 + lane];
        const float2 f1 = __half22float2(k1), f2 = __half22float2(k2);
        float p = f1.x * q0 + f1.y * q1 + f2.x * q2 + f2.y * q3;
#pragma unroll
        for (int o = 16; o > 0; o >>= 1) p += __shfl_xor_sync(0xffffffffu, p, o);
        if (lane == 0) sc[s] = (mask[b * SS + s] != 0) ? p : -3.402823466e38f;
    }
    __syncthreads();

    const float v0 = sc[tid], v1 = sc[tid + 128];
    float lm = fmaxf(v0, v1);
#pragma unroll
    for (int o = 16; o > 0; o >>= 1) lm = fmaxf(lm, __shfl_xor_sync(0xffffffffu, lm, o));
    if (lane == 0) red[w] = lm;
    __syncthreads();
    const float m = fmaxf(fmaxf(red[0], red[1]), fmaxf(red[2], red[3]));
    const float e0 = __expf(v0 - m), e1 = __expf(v1 - m);
    float ls = e0 + e1;
#pragma unroll
    for (int o = 16; o > 0; o >>= 1) ls += __shfl_xor_sync(0xffffffffu, ls, o);
    if (lane == 0) red[4 + w] = ls;
    sc[tid] = e0;
    sc[tid + 128] = e1;
    __syncthreads();
    const float inv = 1.f / (red[4] + red[5] + red[6] + red[7]);

    const __half* Vb = g_V + (size_t)bh * SS * HDD;
    float acc = 0.f;
#pragma unroll 8
    for (int s = 0; s < SS; s++) acc += sc[s] * __half2float(Vb[s * HDD + tid]);
    g_ctx16[(size_t)b * DD + h * HDD + tid] = __float2half(acc * inv);
}

// -------------------- per-step GRU gates + hidden update + fused LayerNorm --------------------
__launch_bounds__(512)
__global__ void gates_ln_kernel(int t, const float* __restrict__ gamma,
                                const float* __restrict__ beta) {
    const int b = blockIdx.x;
    const int d = threadIdx.x;
    const int lane = d & 31, w = d >> 5;
    __shared__ float red[32];
    __shared__ float bcast[2];

    const float xr = g_xg[(size_t)b * G3 + d];
    const float xz = g_xg[(size_t)b * G3 + 512 + d];
    const float xn = g_xg[(size_t)b * G3 + 1024 + d];
    const float hr = g_hg[(size_t)b * G3 + d];
    const float hz = g_hg[(size_t)b * G3 + 512 + d];
    const float hn = g_hg[(size_t)b * G3 + 1024 + d];
    const float r = 1.f / (1.f + __expf(-(xr + hr)));
    const float z = 1.f / (1.f + __expf(-(xz + hz)));
    const float n = tanhf(xn + r * hn);
    const float hprev = g_h[b * DD + d];
    const float hnew = (1.f - z) * n + z * hprev;
    g_h[b * DD + d] = hnew;
    g_h16[b * DD + d] = __float2half(hnew);

    float s1 = hnew, s2 = hnew * hnew;
#pragma unroll
    for (int o = 16; o > 0; o >>= 1) {
        s1 += __shfl_xor_sync(0xffffffffu, s1, o);
        s2 += __shfl_xor_sync(0xffffffffu, s2, o);
    }
    if (lane == 0) { red[w] = s1; red[16 + w] = s2; }
    __syncthreads();
    if (w == 0) {
        float a = (lane < 16) ? red[lane] : 0.f;
        float c = (lane < 16) ? red[16 + lane] : 0.f;
#pragma unroll
        for (int o = 8; o > 0; o >>= 1) {
            a += __shfl_xor_sync(0xffffffffu, a, o);
            c += __shfl_xor_sync(0xffffffffu, c, o);
        }
        if (lane == 0) { bcast[0] = a * (1.f / 512.f); bcast[1] = c * (1.f / 512.f); }
    }
    __syncthreads();
    const float mu = bcast[0];
    const float var = bcast[1] - mu * mu;
    const float rs = rsqrtf(var + 1e-5f);
    g_Hseq[((size_t)t * BB + b) * DD + d] = (hnew - mu) * rs * gamma[d] + beta[d];
}

// -------------------- final: logits GEMM over normed hidden --------------------
__launch_bounds__(512)
__global__ void final_logits_kernel(float* __restrict__ out,
                                    const float* __restrict__ ow,
                                    const float* __restrict__ ob) {
    const int tid = threadIdx.x;
    const int r = blockIdx.x * 8 + (tid & 7);
    const int v = tid >> 3;
    if (v >= VV) return;
    const float* x = g_Hseq + (size_t)r * DD;
    const float* wr = ow + (size_t)v * DD;
    float acc = 0.f;
#pragma unroll 8
    for (int dd = 0; dd < DD; dd += 4) {
        float4 xv = *(const float4*)(x + dd);
        float4 wv = *(const float4*)(wr + dd);
        acc += xv.x * wv.x + xv.y * wv.y + xv.z * wv.z + xv.w * wv.w;
    }
    const int t = r >> 8, b = r & 255;
    out[(size_t)b * (TT * VV) + t * VV + v] = acc + ob[v];
}

// -------------------- launch --------------------
extern "C" void kernel_launch(void* const* d_in, const int* in_sizes, int n_in,
                              void* d_out, int out_size) {
    (void)in_sizes; (void)n_in; (void)out_size;
    const float* init_hidden = (const float*)d_in[0];
    const int* act           = (const int*)d_in[1];
    const float* enc_seq     = (const float*)d_in[2];
    const int* enc_mask      = (const int*)d_in[3];
    const float* emb_table   = (const float*)d_in[4];
    const float* in_proj_w   = (const float*)d_in[5];
    const float* in_proj_b   = (const float*)d_in[6];
    const float* out_proj_w  = (const float*)d_in[7];
    const float* out_proj_b  = (const float*)d_in[8];
    const float* gru_w_ih    = (const float*)d_in[9];
    const float* gru_w_hh    = (const float*)d_in[10];
    const float* gru_b_ih    = (const float*)d_in[11];
    const float* gru_b_hh    = (const float*)d_in[12];
    const float* ln_gamma    = (const float*)d_in[13];
    const float* ln_beta     = (const float*)d_in[14];
    const float* out_w       = (const float*)d_in[15];
    const float* out_b       = (const float*)d_in[16];
    float* out = (float*)d_out;

    // ---- one-time precompute ----
    copy_h_kernel<<<512, 256>>>(init_hidden);
    bcombo_kernel<<<G3 / 4, 128>>>(gru_w_ih, out_proj_b);
    conv_enc_kernel<<<(BB * SS * DD) / 8 / 256, 256>>>(enc_seq);
    conv_wkv_kernel<<<(1024 * DD) / 8 / 256, 256>>>(in_proj_w + (size_t)512 * 512);
    conv_wqh_kernel<<<(2048 * DD) / 8 / 256, 256>>>(in_proj_w, gru_w_hh);
    gemm_tn<0><<<dim3(24, 1), 256>>>(emb_table, 512, gru_w_ih, 1024, gru_b_ih, 50, G3);
    gemm_nn_wcombo<<<dim3(8, 24), 256>>>(gru_w_ih + 512, out_proj_w);
    conv_wc_kernel<<<(G3 * DD) / 8 / 256, 256>>>();
    hmma_kv_kernel<<<dim3(16, 1024), 128>>>(in_proj_b + 512);

    // ---- 127 serial steps ----
    for (int t = 0; t < TT; t++) {
        hmma_step<0><<<dim3(32, 4), 128>>>(in_proj_b, gru_b_hh, nullptr, 0);
        attn_kernel<<<BB * HH, 128>>>(enc_mask);
        hmma_step<1><<<dim3(24, 4), 128>>>(nullptr, nullptr, act, t);
        gates_ln_kernel<<<BB, 512>>>(t, ln_gamma, ln_beta);
    }

    // ---- final logits ----
    final_logits_kernel<<<(TT * BB) / 8, 512>>>(out, out_w, out_b);
}

// round 5
// speedup vs baseline: 2.0448x; 1.3385x over previous
#include <cuda_runtime.h>
#include <cuda_fp16.h>
#include <cuda_fp8.h>

#define BB 256
#define TT 127
#define TFULL 128
#define SS 256
#define DD 512
#define VV 50
#define HH 4
#define HDD 128
#define G3 1536

// -------------------- device scratch (no allocations allowed) --------------------
__device__ __align__(128) unsigned char g_K8[(size_t)BB * HH * SS * HDD]; // fp8 K [b][h][s][hd]
__device__ __align__(128) __half g_V[(size_t)BB * HH * SS * HDD];   // fp16 V
__device__ __align__(128) __half g_enc_h[(size_t)BB * SS * DD];     // enc_seq fp16
__device__ __align__(128) __half g_Wkv[(size_t)1024 * DD];          // [Wk;Wv] fp16
__device__ __align__(128) __half g_Wqh16[(size_t)2048 * DD];        // [Wq; W_hh] fp16
__device__ __align__(128) __half g_Wc16[(size_t)G3 * DD];           // Wcombo fp16
__device__ __align__(128) __half g_h16[BB * DD];                    // fp16 copy of h
__device__ __align__(128) __half g_ctx16[BB * DD];                  // fp16 ctx
__device__ __align__(128) float g_h[BB * DD];
__device__ __align__(128) float g_q[BB * DD];        // pre-scaled q
__device__ __align__(128) float g_hg[BB * G3];       // h @ W_hh^T + b_hh
__device__ __align__(128) float g_Hseq[(size_t)TT * BB * DD];       // RAW hidden (LN deferred)
__device__ __align__(128) float g_tproj[VV * G3];
__device__ __align__(128) float g_Wcombo[(size_t)G3 * DD];
__device__ __align__(128) float g_bcombo[G3];

// -------------------- small helpers --------------------
__global__ void copy_h_kernel(const float* __restrict__ src) {
    int i = blockIdx.x * blockDim.x + threadIdx.x;
    float v = src[i];
    g_h[i] = v;
    g_h16[i] = __float2half(v);
}

__global__ void bcombo_kernel(const float* __restrict__ wih, const float* __restrict__ bo) {
    int n = blockIdx.x * 4 + (threadIdx.x >> 5);
    int lane = threadIdx.x & 31;
    const float* r = wih + (size_t)n * 1024 + 512;
    float p = 0.f;
    for (int k = lane; k < DD; k += 32) p += r[k] * bo[k];
#pragma unroll
    for (int o = 16; o > 0; o >>= 1) p += __shfl_xor_sync(0xffffffffu, p, o);
    if (lane == 0) g_bcombo[n] = p;
}

__device__ __forceinline__ uint4 cvt8(const float* src) {
    float4 f0 = *(const float4*)(src);
    float4 f1 = *(const float4*)(src + 4);
    __half2 h0 = __floats2half2_rn(f0.x, f0.y);
    __half2 h1 = __floats2half2_rn(f0.z, f0.w);
    __half2 h2 = __floats2half2_rn(f1.x, f1.y);
    __half2 h3 = __floats2half2_rn(f1.z, f1.w);
    return make_uint4(*(unsigned*)&h0, *(unsigned*)&h1, *(unsigned*)&h2, *(unsigned*)&h3);
}

__global__ void conv_enc_kernel(const float* __restrict__ src) {
    size_t i = (size_t)(blockIdx.x * blockDim.x + threadIdx.x) * 8;
    *(uint4*)(g_enc_h + i) = cvt8(src + i);
}

__global__ void conv_wkv_kernel(const float* __restrict__ src) {
    size_t i = (size_t)(blockIdx.x * blockDim.x + threadIdx.x) * 8;
    *(uint4*)(g_Wkv + i) = cvt8(src + i);
}

__global__ void conv_wqh_kernel(const float* __restrict__ inproj,
                                const float* __restrict__ whh) {
    size_t i8 = (size_t)(blockIdx.x * blockDim.x + threadIdx.x);
    size_t n = i8 >> 6;
    size_t k = (i8 & 63) * 8;
    const float* src = (n < 512) ? (inproj + n * 512 + k) : (whh + (n - 512) * 512 + k);
    *(uint4*)(g_Wqh16 + n * 512 + k) = cvt8(src);
}

__global__ void conv_wc_kernel() {
    size_t i = (size_t)(blockIdx.x * blockDim.x + threadIdx.x) * 8;
    *(uint4*)(g_Wc16 + i) = cvt8(g_Wcombo + i);
}

// -------------------- fp32 TN GEMM (precompute: tproj) --------------------
__launch_bounds__(256)
__global__ void gemm_tproj(const float* __restrict__ A, const float* __restrict__ W,
                           const float* __restrict__ bias, int M, int N) {
    __shared__ float As[16][68];
    __shared__ float Ws[16][68];
    const int bm = blockIdx.y * 64, bn = blockIdx.x * 64;
    const int tid = threadIdx.x;
    const int tx = tid & 15, ty = tid >> 4;
    const int lr = tid >> 2;
    const int lk = (tid & 3) << 2;

    float acc[4][4];
#pragma unroll
    for (int i = 0; i < 4; i++)
#pragma unroll
        for (int j = 0; j < 4; j++) acc[i][j] = 0.f;

    const int gm_l = bm + lr;
    const int gn_l = bn + lr;
    const float* Arow = (gm_l < M) ? (A + (size_t)gm_l * 512) : nullptr;
    const float* Wrow = W + (size_t)gn_l * 1024;
    const bool wok = (gn_l < N);

    for (int k0 = 0; k0 < 512; k0 += 16) {
        float4 av = make_float4(0.f, 0.f, 0.f, 0.f);
        if (Arow) av = *(const float4*)(Arow + k0 + lk);
        float4 wv = make_float4(0.f, 0.f, 0.f, 0.f);
        if (wok) wv = *(const float4*)(Wrow + k0 + lk);
        As[lk + 0][lr] = av.x; As[lk + 1][lr] = av.y;
        As[lk + 2][lr] = av.z; As[lk + 3][lr] = av.w;
        Ws[lk + 0][lr] = wv.x; Ws[lk + 1][lr] = wv.y;
        Ws[lk + 2][lr] = wv.z; Ws[lk + 3][lr] = wv.w;
        __syncthreads();
#pragma unroll
        for (int kk = 0; kk < 16; kk++) {
            float4 a4 = *(const float4*)&As[kk][ty * 4];
            float4 w4 = *(const float4*)&Ws[kk][tx * 4];
            acc[0][0] += a4.x * w4.x; acc[0][1] += a4.x * w4.y;
            acc[0][2] += a4.x * w4.z; acc[0][3] += a4.x * w4.w;
            acc[1][0] += a4.y * w4.x; acc[1][1] += a4.y * w4.y;
            acc[1][2] += a4.y * w4.z; acc[1][3] += a4.y * w4.w;
            acc[2][0] += a4.z * w4.x; acc[2][1] += a4.z * w4.y;
            acc[2][2] += a4.z * w4.z; acc[2][3] += a4.z * w4.w;
            acc[3][0] += a4.w * w4.x; acc[3][1] += a4.w * w4.y;
            acc[3][2] += a4.w * w4.z; acc[3][3] += a4.w * w4.w;
        }
        __syncthreads();
    }

#pragma unroll
    for (int i = 0; i < 4; i++) {
        const int gm = bm + ty * 4 + i;
        if (gm >= M) continue;
#pragma unroll
        for (int j = 0; j < 4; j++) {
            const int gn = bn + tx * 4 + j;
            if (gn >= N) continue;
            g_tproj[(size_t)gm * G3 + gn] = acc[i][j] + bias[gn];
        }
    }
}

// -------------------- NN GEMM for Wcombo = W_c @ Wo --------------------
__launch_bounds__(256)
__global__ void gemm_nn_wcombo(const float* __restrict__ A,
                               const float* __restrict__ Bm) {
    __shared__ float As[64][20];
    __shared__ float Bs[16][68];
    const int bm = blockIdx.y * 64, bn = blockIdx.x * 64;
    const int tid = threadIdx.x;
    const int tx = tid & 15, ty = tid >> 4;
    const int lr = tid >> 2, lk = (tid & 3) << 2;
    float acc[4][4];
#pragma unroll
    for (int i = 0; i < 4; i++)
#pragma unroll
        for (int j = 0; j < 4; j++) acc[i][j] = 0.f;

    const float* Arow = A + (size_t)(bm + lr) * 1024;
    for (int k0 = 0; k0 < 512; k0 += 16) {
        float4 av = *(const float4*)(Arow + k0 + lk);
        *(float4*)&As[lr][lk] = av;
        float4 bv = *(const float4*)(Bm + (size_t)(k0 + ty) * 512 + bn + tx * 4);
        *(float4*)&Bs[ty][tx * 4] = bv;
        __syncthreads();
#pragma unroll
        for (int kk = 0; kk < 16; kk++) {
            float a0 = As[ty * 4 + 0][kk], a1 = As[ty * 4 + 1][kk];
            float a2 = As[ty * 4 + 2][kk], a3 = As[ty * 4 + 3][kk];
            float4 w4 = *(const float4*)&Bs[kk][tx * 4];
            acc[0][0] += a0 * w4.x; acc[0][1] += a0 * w4.y; acc[0][2] += a0 * w4.z; acc[0][3] += a0 * w4.w;
            acc[1][0] += a1 * w4.x; acc[1][1] += a1 * w4.y; acc[1][2] += a1 * w4.z; acc[1][3] += a1 * w4.w;
            acc[2][0] += a2 * w4.x; acc[2][1] += a2 * w4.y; acc[2][2] += a2 * w4.z; acc[2][3] += a2 * w4.w;
            acc[3][0] += a3 * w4.x; acc[3][1] += a3 * w4.y; acc[3][2] += a3 * w4.z; acc[3][3] += a3 * w4.w;
        }
        __syncthreads();
    }
#pragma unroll
    for (int i = 0; i < 4; i++)
#pragma unroll
        for (int j = 0; j < 4; j++)
            g_Wcombo[(size_t)(bm + ty * 4 + i) * 512 + bn + tx * 4 + j] = acc[i][j];
}

// -------------------- fp16 tensor-core MMA helper --------------------
__device__ __forceinline__ void mma16816(float* d, unsigned a0, unsigned a1, unsigned a2,
                                         unsigned a3, unsigned b0, unsigned b1) {
    asm volatile(
        "mma.sync.aligned.m16n8k16.row.col.f32.f16.f16.f32 "
        "{%0,%1,%2,%3}, {%4,%5,%6,%7}, {%8,%9}, {%0,%1,%2,%3};\n"
        : "+f"(d[0]), "+f"(d[1]), "+f"(d[2]), "+f"(d[3])
        : "r"(a0), "r"(a1), "r"(a2), "r"(a3), "r"(b0), "r"(b1));
}

// -------------------- KV precompute: fp16 TC GEMM, K->fp8, V->fp16 --------------------
__launch_bounds__(128)
__global__ void hmma_kv_kernel(const float* __restrict__ bias /* in_proj_b+512 */) {
    __shared__ __half As[64][72];
    __shared__ __half Bs[64][72];
    const int bm = blockIdx.y * 64, bn = blockIdx.x * 64;
    const int tid = threadIdx.x, lane = tid & 31, w = tid >> 5;
    const int gr = lane >> 2, q2 = (lane & 3) * 2;
    const int wm = (w >> 1) * 32, wn = (w & 1) * 32;
    const int lr = tid >> 1, lc = (tid & 1) * 32;

    float acc[2][4][4];
#pragma unroll
    for (int mi = 0; mi < 2; mi++)
#pragma unroll
        for (int nj = 0; nj < 4; nj++)
#pragma unroll
            for (int r = 0; r < 4; r++) acc[mi][nj][r] = 0.f;

    for (int kt = 0; kt < 512; kt += 64) {
        const uint4* ag = (const uint4*)(g_enc_h + (size_t)(bm + lr) * 512 + kt + lc);
        const uint4* bg = (const uint4*)(g_Wkv + (size_t)(bn + lr) * 512 + kt + lc);
        uint4 a0v = ag[0], a1v = ag[1], a2v = ag[2], a3v = ag[3];
        uint4 b0v = bg[0], b1v = bg[1], b2v = bg[2], b3v = bg[3];
        __syncthreads();
        *(uint4*)&As[lr][lc + 0]  = a0v; *(uint4*)&As[lr][lc + 8]  = a1v;
        *(uint4*)&As[lr][lc + 16] = a2v; *(uint4*)&As[lr][lc + 24] = a3v;
        *(uint4*)&Bs[lr][lc + 0]  = b0v; *(uint4*)&Bs[lr][lc + 8]  = b1v;
        *(uint4*)&Bs[lr][lc + 16] = b2v; *(uint4*)&Bs[lr][lc + 24] = b3v;
        __syncthreads();
#pragma unroll
        for (int ks = 0; ks < 4; ks++) {
            const int kk = ks * 16;
            unsigned b0[4], b1[4];
#pragma unroll
            for (int nj = 0; nj < 4; nj++) {
                const int n = wn + nj * 8 + gr;
                b0[nj] = *(const unsigned*)&Bs[n][kk + q2];
                b1[nj] = *(const unsigned*)&Bs[n][kk + q2 + 8];
            }
#pragma unroll
            for (int mi = 0; mi < 2; mi++) {
                const int rm = wm + mi * 16;
                unsigned a0 = *(const unsigned*)&As[rm + gr][kk + q2];
                unsigned a1 = *(const unsigned*)&As[rm + gr + 8][kk + q2];
                unsigned a2 = *(const unsigned*)&As[rm + gr][kk + q2 + 8];
                unsigned a3 = *(const unsigned*)&As[rm + gr + 8][kk + q2 + 8];
#pragma unroll
                for (int nj = 0; nj < 4; nj++)
                    mma16816(acc[mi][nj], a0, a1, a2, a3, b0[nj], b1[nj]);
            }
        }
    }

#pragma unroll
    for (int mi = 0; mi < 2; mi++) {
#pragma unroll
        for (int nj = 0; nj < 4; nj++) {
            const int n0 = bn + wn + nj * 8 + q2;
            const float bi0 = bias[n0], bi1 = bias[n0 + 1];
#pragma unroll
            for (int half_row = 0; half_row < 2; half_row++) {
                const int m = bm + wm + mi * 16 + gr + half_row * 8;
                const float v0 = acc[mi][nj][half_row * 2 + 0] + bi0;
                const float v1 = acc[mi][nj][half_row * 2 + 1] + bi1;
                const int b = m >> 8, s = m & 255;
                if (n0 < 512) {
                    const int h = n0 >> 7, hd = n0 & 127;
                    __nv_fp8x2_e4m3 p8(make_float2(v0, v1));
                    *(unsigned short*)(g_K8 + (((size_t)(b * HH + h) * SS + s) * HDD + hd)) = p8.__x;
                } else {
                    const int nn = n0 - 512;
                    const int h = nn >> 7, hd = nn & 127;
                    __half2 hv = __floats2half2_rn(v0, v1);
                    *(__half2*)(g_V + (((size_t)(b * HH + h) * SS + s) * HDD + hd)) = hv;
                }
            }
        }
    }
}

// -------------------- per-step QH GEMM (tensor core) --------------------
// A=g_h16, W=g_Wqh16, N=2048: n<512 -> g_q (+bq, scaled); else g_hg (+b_hh)
__launch_bounds__(128)
__global__ void hmma_step_qh(const float* __restrict__ bias,
                             const float* __restrict__ bias2) {
    __shared__ __half As[64][72];
    __shared__ __half Bs[64][72];
    const int bm = blockIdx.y * 64, bn = blockIdx.x * 64;
    const int tid = threadIdx.x, lane = tid & 31, w = tid >> 5;
    const int gr = lane >> 2, q2 = (lane & 3) * 2;
    const int wm = (w >> 1) * 32, wn = (w & 1) * 32;
    const int lr = tid >> 1, lc = (tid & 1) * 32;

    float acc[2][4][4];
#pragma unroll
    for (int mi = 0; mi < 2; mi++)
#pragma unroll
        for (int nj = 0; nj < 4; nj++)
#pragma unroll
            for (int r = 0; r < 4; r++) acc[mi][nj][r] = 0.f;

    for (int kt = 0; kt < 512; kt += 64) {
        const uint4* ag = (const uint4*)(g_h16 + (size_t)(bm + lr) * 512 + kt + lc);
        const uint4* bg = (const uint4*)(g_Wqh16 + (size_t)(bn + lr) * 512 + kt + lc);
        uint4 a0v = ag[0], a1v = ag[1], a2v = ag[2], a3v = ag[3];
        uint4 b0v = bg[0], b1v = bg[1], b2v = bg[2], b3v = bg[3];
        __syncthreads();
        *(uint4*)&As[lr][lc + 0]  = a0v; *(uint4*)&As[lr][lc + 8]  = a1v;
        *(uint4*)&As[lr][lc + 16] = a2v; *(uint4*)&As[lr][lc + 24] = a3v;
        *(uint4*)&Bs[lr][lc + 0]  = b0v; *(uint4*)&Bs[lr][lc + 8]  = b1v;
        *(uint4*)&Bs[lr][lc + 16] = b2v; *(uint4*)&Bs[lr][lc + 24] = b3v;
        __syncthreads();
#pragma unroll
        for (int ks = 0; ks < 4; ks++) {
            const int kk = ks * 16;
            unsigned b0[4], b1[4];
#pragma unroll
            for (int nj = 0; nj < 4; nj++) {
                const int n = wn + nj * 8 + gr;
                b0[nj] = *(const unsigned*)&Bs[n][kk + q2];
                b1[nj] = *(const unsigned*)&Bs[n][kk + q2 + 8];
            }
#pragma unroll
            for (int mi = 0; mi < 2; mi++) {
                const int rm = wm + mi * 16;
                unsigned a0 = *(const unsigned*)&As[rm + gr][kk + q2];
                unsigned a1 = *(const unsigned*)&As[rm + gr + 8][kk + q2];
                unsigned a2 = *(const unsigned*)&As[rm + gr][kk + q2 + 8];
                unsigned a3 = *(const unsigned*)&As[rm + gr + 8][kk + q2 + 8];
#pragma unroll
                for (int nj = 0; nj < 4; nj++)
                    mma16816(acc[mi][nj], a0, a1, a2, a3, b0[nj], b1[nj]);
            }
        }
    }

#pragma unroll
    for (int mi = 0; mi < 2; mi++) {
#pragma unroll
        for (int nj = 0; nj < 4; nj++) {
            const int n0 = bn + wn + nj * 8 + q2;
#pragma unroll
            for (int half_row = 0; half_row < 2; half_row++) {
                const int m = bm + wm + mi * 16 + gr + half_row * 8;
                const float v0 = acc[mi][nj][half_row * 2 + 0];
                const float v1 = acc[mi][nj][half_row * 2 + 1];
                if (n0 < 512) {
                    float2 o;
                    o.x = (v0 + bias[n0]) * 0.088388347648318447f;
                    o.y = (v1 + bias[n0 + 1]) * 0.088388347648318447f;
                    *(float2*)(g_q + (size_t)m * DD + n0) = o;
                } else {
                    const int nn = n0 - 512;
                    float2 o;
                    o.x = v0 + bias2[nn];
                    o.y = v1 + bias2[nn + 1];
                    *(float2*)(g_hg + (size_t)m * G3 + nn) = o;
                }
            }
        }
    }
}

// -------------------- per-step attention (fp8 K, fp16 V) --------------------
__launch_bounds__(256)
__global__ void attn_kernel(const int* __restrict__ mask) {
    const int bh = blockIdx.x;
    const int b = bh >> 2;
    __shared__ float sq[HDD];
    __shared__ float sc[SS];
    __shared__ float red[16];
    __shared__ float part[256];
    const int tid = threadIdx.x, lane = tid & 31, w = tid >> 5;

    if (tid < HDD) sq[tid] = g_q[(size_t)b * DD + (bh & 3) * HDD + tid];
    __syncthreads();
    const float4 q4 = *(const float4*)&sq[lane * 4];

    // scores: 8 warps, each warp one s-row at a time
    const unsigned char* K8 = g_K8 + (size_t)bh * SS * HDD;
    for (int s = w; s < SS; s += 8) {
        const unsigned k4 = *(const unsigned*)(K8 + s * HDD + lane * 4);
        __half2_raw lo = __nv_cvt_fp8x2_to_halfraw2((__nv_fp8x2_storage_t)(k4 & 0xFFFFu), __NV_E4M3);
        __half2_raw hi = __nv_cvt_fp8x2_to_halfraw2((__nv_fp8x2_storage_t)(k4 >> 16), __NV_E4M3);
        const float2 f01 = __half22float2(*(__half2*)&lo);
        const float2 f23 = __half22float2(*(__half2*)&hi);
        float p = f01.x * q4.x + f01.y * q4.y + f23.x * q4.z + f23.y * q4.w;
#pragma unroll
        for (int o = 16; o > 0; o >>= 1) p += __shfl_xor_sync(0xffffffffu, p, o);
        if (lane == 0) sc[s] = (mask[b * SS + s] != 0) ? p : -3.402823466e38f;
    }
    __syncthreads();

    // softmax over 256 (one s per thread)
    const float v = sc[tid];
    float lm = v;
#pragma unroll
    for (int o = 16; o > 0; o >>= 1) lm = fmaxf(lm, __shfl_xor_sync(0xffffffffu, lm, o));
    if (lane == 0) red[w] = lm;
    __syncthreads();
    float m = red[0];
#pragma unroll
    for (int i = 1; i < 8; i++) m = fmaxf(m, red[i]);
    const float e = __expf(v - m);
    sc[tid] = e;
    float ls = e;
#pragma unroll
    for (int o = 16; o > 0; o >>= 1) ls += __shfl_xor_sync(0xffffffffu, ls, o);
    if (lane == 0) red[8 + w] = ls;
    __syncthreads();
    float tot = red[8];
#pragma unroll
    for (int i = 9; i < 16; i++) tot += red[i];
    const float inv = 1.f / tot;

    // ctx: split S across two thread halves
    const int hd = tid & 127, seg = tid >> 7;
    const __half* Vb = g_V + (size_t)bh * SS * HDD + (size_t)seg * 128 * HDD;
    const float* scp = sc + seg * 128;
    float acc = 0.f;
#pragma unroll 16
    for (int s = 0; s < 128; s++) acc += scp[s] * __half2float(Vb[s * HDD + hd]);
    part[tid] = acc;
    __syncthreads();
    if (tid < 128)
        g_ctx16[(size_t)b * DD + (bh & 3) * HDD + tid] =
            __float2half((part[tid] + part[tid + 128]) * inv);
}

// -------------------- per-step XG GEMM + fused GRU gates (LN deferred) --------------------
// Block: 64 m-rows x 64 d-cols, computing all 3 gate segments (d, 512+d, 1024+d).
__launch_bounds__(128)
__global__ void hmma_xg_gates(const int* __restrict__ act, int t) {
    __shared__ __half As[64][72];
    __shared__ __half Bs[3][64][72];
    const int d0 = blockIdx.x * 64;        // 0..448
    const int bm = blockIdx.y * 64;
    const int tid = threadIdx.x, lane = tid & 31, w = tid >> 5;
    const int gr = lane >> 2, q2 = (lane & 3) * 2;
    const int wm = (w >> 1) * 32, wn = (w & 1) * 32;
    const int lr = tid >> 1, lc = (tid & 1) * 32;

    float acc[3][2][4][4];
#pragma unroll
    for (int sg = 0; sg < 3; sg++)
#pragma unroll
        for (int mi = 0; mi < 2; mi++)
#pragma unroll
            for (int nj = 0; nj < 4; nj++)
#pragma unroll
                for (int r = 0; r < 4; r++) acc[sg][mi][nj][r] = 0.f;

    for (int kt = 0; kt < 512; kt += 64) {
        const uint4* ag = (const uint4*)(g_ctx16 + (size_t)(bm + lr) * 512 + kt + lc);
        uint4 av0 = ag[0], av1 = ag[1], av2 = ag[2], av3 = ag[3];
        uint4 bv[3][4];
#pragma unroll
        for (int sg = 0; sg < 3; sg++) {
            const uint4* bg = (const uint4*)(g_Wc16 + (size_t)(sg * 512 + d0 + lr) * 512 + kt + lc);
            bv[sg][0] = bg[0]; bv[sg][1] = bg[1]; bv[sg][2] = bg[2]; bv[sg][3] = bg[3];
        }
        __syncthreads();
        *(uint4*)&As[lr][lc + 0]  = av0; *(uint4*)&As[lr][lc + 8]  = av1;
        *(uint4*)&As[lr][lc + 16] = av2; *(uint4*)&As[lr][lc + 24] = av3;
#pragma unroll
        for (int sg = 0; sg < 3; sg++) {
            *(uint4*)&Bs[sg][lr][lc + 0]  = bv[sg][0];
            *(uint4*)&Bs[sg][lr][lc + 8]  = bv[sg][1];
            *(uint4*)&Bs[sg][lr][lc + 16] = bv[sg][2];
            *(uint4*)&Bs[sg][lr][lc + 24] = bv[sg][3];
        }
        __syncthreads();
#pragma unroll
        for (int ks = 0; ks < 4; ks++) {
            const int kk = ks * 16;
            unsigned a0[2], a1[2], a2[2], a3[2];
#pragma unroll
            for (int mi = 0; mi < 2; mi++) {
                const int rm = wm + mi * 16;
                a0[mi] = *(const unsigned*)&As[rm + gr][kk + q2];
                a1[mi] = *(const unsigned*)&As[rm + gr + 8][kk + q2];
                a2[mi] = *(const unsigned*)&As[rm + gr][kk + q2 + 8];
                a3[mi] = *(const unsigned*)&As[rm + gr + 8][kk + q2 + 8];
            }
#pragma unroll
            for (int sg = 0; sg < 3; sg++) {
#pragma unroll
                for (int nj = 0; nj < 4; nj++) {
                    const int n = wn + nj * 8 + gr;
                    const unsigned b0 = *(const unsigned*)&Bs[sg][n][kk + q2];
                    const unsigned b1 = *(const unsigned*)&Bs[sg][n][kk + q2 + 8];
#pragma unroll
                    for (int mi = 0; mi < 2; mi++)
                        mma16816(acc[sg][mi][nj], a0[mi], a1[mi], a2[mi], a3[mi], b0, b1);
                }
            }
        }
    }

    // epilogue: gates + hidden update (LN deferred to final)
#pragma unroll
    for (int mi = 0; mi < 2; mi++) {
#pragma unroll
        for (int hrow = 0; hrow < 2; hrow++) {
            const int m = bm + wm + mi * 16 + gr + hrow * 8;
            const int a = act[m * TFULL + t];
#pragma unroll
            for (int nj = 0; nj < 4; nj++) {
                const int d = d0 + wn + nj * 8 + q2;
                const float2 t0 = *(const float2*)&g_tproj[(size_t)a * G3 + d];
                const float2 t1 = *(const float2*)&g_tproj[(size_t)a * G3 + 512 + d];
                const float2 t2 = *(const float2*)&g_tproj[(size_t)a * G3 + 1024 + d];
                const float2 c0 = *(const float2*)&g_bcombo[d];
                const float2 c1 = *(const float2*)&g_bcombo[512 + d];
                const float2 c2 = *(const float2*)&g_bcombo[1024 + d];
                const float2 hr2v = *(const float2*)&g_hg[(size_t)m * G3 + d];
                const float2 hz2v = *(const float2*)&g_hg[(size_t)m * G3 + 512 + d];
                const float2 hn2v = *(const float2*)&g_hg[(size_t)m * G3 + 1024 + d];
                const float2 hp2v = *(const float2*)&g_h[(size_t)m * DD + d];
                float hnew[2];
#pragma unroll
                for (int e = 0; e < 2; e++) {
                    const int ai = hrow * 2 + e;
                    const float xr = acc[0][mi][nj][ai] + (e ? c0.y : c0.x) + (e ? t0.y : t0.x);
                    const float xz = acc[1][mi][nj][ai] + (e ? c1.y : c1.x) + (e ? t1.y : t1.x);
                    const float xn = acc[2][mi][nj][ai] + (e ? c2.y : c2.x) + (e ? t2.y : t2.x);
                    const float hr_ = e ? hr2v.y : hr2v.x;
                    const float hz_ = e ? hz2v.y : hz2v.x;
                    const float hn_ = e ? hn2v.y : hn2v.x;
                    const float hp_ = e ? hp2v.y : hp2v.x;
                    const float r = 1.f / (1.f + __expf(-(xr + hr_)));
                    const float z = 1.f / (1.f + __expf(-(xz + hz_)));
                    const float n = tanhf(xn + r * hn_);
                    hnew[e] = (1.f - z) * n + z * hp_;
                }
                *(float2*)(g_h + (size_t)m * DD + d) = make_float2(hnew[0], hnew[1]);
                *(__half2*)(g_h16 + (size_t)m * DD + d) = __floats2half2_rn(hnew[0], hnew[1]);
                *(float2*)(g_Hseq + ((size_t)t * BB + m) * DD + d) = make_float2(hnew[0], hnew[1]);
            }
        }
    }
}

// -------------------- final: LayerNorm + logits (batched over T*B rows) --------------------
__launch_bounds__(256)
__global__ void final_kernel(float* __restrict__ out,
                             const float* __restrict__ gamma, const float* __restrict__ beta,
                             const float* __restrict__ ow, const float* __restrict__ ob) {
    const int row = blockIdx.x;            // t*BB + b
    const float* x = g_Hseq + (size_t)row * DD;
    __shared__ float sn[DD];
    __shared__ float red[16];
    const int tid = threadIdx.x, lane = tid & 31, w = tid >> 5;

    const float v0 = x[tid], v1 = x[tid + 256];
    float s1 = v0 + v1, s2 = v0 * v0 + v1 * v1;
#pragma unroll
    for (int o = 16; o > 0; o >>= 1) {
        s1 += __shfl_xor_sync(0xffffffffu, s1, o);
        s2 += __shfl_xor_sync(0xffffffffu, s2, o);
    }
    if (lane == 0) { red[w] = s1; red[8 + w] = s2; }
    __syncthreads();
    float mu = 0.f, ms = 0.f;
#pragma unroll
    for (int i = 0; i < 8; i++) { mu += red[i]; ms += red[8 + i]; }
    mu *= (1.f / 512.f); ms *= (1.f / 512.f);
    const float rs = rsqrtf(ms - mu * mu + 1e-5f);
    sn[tid]       = (v0 - mu) * rs * gamma[tid]       + beta[tid];
    sn[tid + 256] = (v1 - mu) * rs * gamma[tid + 256] + beta[tid + 256];
    __syncthreads();

    const int t = row >> 8, b = row & 255;
    for (int vv = w; vv < VV; vv += 8) {
        const float* wr = ow + (size_t)vv * DD;
        float p = 0.f;
#pragma unroll 16
        for (int d = lane; d < DD; d += 32) p += sn[d] * wr[d];
#pragma unroll
        for (int o = 16; o > 0; o >>= 1) p += __shfl_xor_sync(0xffffffffu, p, o);
        if (lane == 0) out[(size_t)b * (TT * VV) + t * VV + vv] = p + ob[vv];
    }
}

// -------------------- launch --------------------
extern "C" void kernel_launch(void* const* d_in, const int* in_sizes, int n_in,
                              void* d_out, int out_size) {
    (void)in_sizes; (void)n_in; (void)out_size;
    const float* init_hidden = (const float*)d_in[0];
    const int* act           = (const int*)d_in[1];
    const float* enc_seq     = (const float*)d_in[2];
    const int* enc_mask      = (const int*)d_in[3];
    const float* emb_table   = (const float*)d_in[4];
    const float* in_proj_w   = (const float*)d_in[5];
    const float* in_proj_b   = (const float*)d_in[6];
    const float* out_proj_w  = (const float*)d_in[7];
    const float* out_proj_b  = (const float*)d_in[8];
    const float* gru_w_ih    = (const float*)d_in[9];
    const float* gru_w_hh    = (const float*)d_in[10];
    const float* gru_b_ih    = (const float*)d_in[11];
    const float* gru_b_hh    = (const float*)d_in[12];
    const float* ln_gamma    = (const float*)d_in[13];
    const float* ln_beta     = (const float*)d_in[14];
    const float* out_w       = (const float*)d_in[15];
    const float* out_b       = (const float*)d_in[16];
    float* out = (float*)d_out;

    // ---- one-time precompute ----
    copy_h_kernel<<<512, 256>>>(init_hidden);
    bcombo_kernel<<<G3 / 4, 128>>>(gru_w_ih, out_proj_b);
    conv_enc_kernel<<<(BB * SS * DD) / 8 / 256, 256>>>(enc_seq);
    conv_wkv_kernel<<<(1024 * DD) / 8 / 256, 256>>>(in_proj_w + (size_t)512 * 512);
    conv_wqh_kernel<<<(2048 * DD) / 8 / 256, 256>>>(in_proj_w, gru_w_hh);
    gemm_tproj<<<dim3(24, 1), 256>>>(emb_table, gru_w_ih, gru_b_ih, 50, G3);
    gemm_nn_wcombo<<<dim3(8, 24), 256>>>(gru_w_ih + 512, out_proj_w);
    conv_wc_kernel<<<(G3 * DD) / 8 / 256, 256>>>();
    hmma_kv_kernel<<<dim3(16, 1024), 128>>>(in_proj_b + 512);

    // ---- 127 serial steps (3 kernels each) ----
    for (int t = 0; t < TT; t++) {
        hmma_step_qh<<<dim3(32, 4), 128>>>(in_proj_b, gru_b_hh);
        attn_kernel<<<BB * HH, 256>>>(enc_mask);
        hmma_xg_gates<<<dim3(8, 4), 128>>>(act, t);
    }

    // ---- final: LN + logits ----
    final_kernel<<<TT * BB, 256>>>(out, ln_gamma, ln_beta, out_w, out_b);
}